// round 9
// baseline (speedup 1.0000x reference)
#include <cuda_runtime.h>
#include <cuda_bf16.h>
#include <cstdint>

#define BSZ 16
#define SEQ 2048
#define DKE 64
#define KR_ROWS 2176

// -------- device-global bf16 split scratch --------
__device__ __align__(16) __nv_bfloat16 g_qhi[BSZ * SEQ * DKE];
__device__ __align__(16) __nv_bfloat16 g_qlo[BSZ * SEQ * DKE];
__device__ __align__(16) __nv_bfloat16 g_khi[BSZ * SEQ * DKE];
__device__ __align__(16) __nv_bfloat16 g_klo[BSZ * SEQ * DKE];
__device__ __align__(16) __nv_bfloat16 g_vthi[BSZ * DKE * SEQ];  // [b][d][t]
__device__ __align__(16) __nv_bfloat16 g_vtlo[BSZ * DKE * SEQ];
__device__ __align__(16) __nv_bfloat16 g_krthi[KR_ROWS * DKE];   // [c][d], c>=SEQ zero

__device__ __forceinline__ uint32_t smem_to_u32(const void* p) {
    uint32_t a;
    asm("{ .reg .u64 t; cvta.to.shared.u64 t, %1; cvt.u32.u64 %0, t; }" : "=r"(a) : "l"(p));
    return a;
}

#define LDSM4(r0, r1, r2, r3, addr) \
    asm volatile("ldmatrix.sync.aligned.m8n8.x4.shared.b16 {%0,%1,%2,%3}, [%4];" \
                 : "=r"(r0), "=r"(r1), "=r"(r2), "=r"(r3) : "r"(addr))

#define MMA16816(d, a, bb0, bb1) \
    asm volatile("mma.sync.aligned.m16n8k16.row.col.f32.bf16.bf16.f32 " \
                 "{%0,%1,%2,%3},{%4,%5,%6,%7},{%8,%9},{%0,%1,%2,%3};" \
                 : "+f"((d)[0]), "+f"((d)[1]), "+f"((d)[2]), "+f"((d)[3]) \
                 : "r"((a)[0]), "r"((a)[1]), "r"((a)[2]), "r"((a)[3]), "r"(bb0), "r"(bb1))

#define CP16(dst, src) \
    asm volatile("cp.async.ca.shared.global [%0], [%1], 16;" :: "r"(dst), "l"(src))
#define CP_COMMIT() asm volatile("cp.async.commit_group;")
#define CP_WAIT0()  asm volatile("cp.async.wait_group 0;")

#define C_SCALE 0.1803368801111204f  /* log2(e)/sqrt(64) */

__device__ __forceinline__ float fexp2(float x) {
    x = fmaxf(x, -126.0f);
    float n = rintf(x), f = x - n;
    float r = 0.00133335581464f;
    r = fmaf(r, f, 0.00961812910763f);
    r = fmaf(r, f, 0.0555041086648f);
    r = fmaf(r, f, 0.2402265069591f);
    r = fmaf(r, f, 0.69314718056f);
    r = fmaf(r, f, 1.0f);
    return r * __int_as_float(((int)n + 127) << 23);
}

// -------- merged prologue: 3208 blocks x 256 threads --------
__global__ void prologue_kernel(const float* __restrict__ Q, const float* __restrict__ K,
                                const float* __restrict__ V, const float* __restrict__ Kr) {
    __shared__ float tile[32][33];
    const int bx = blockIdx.x, tid = threadIdx.x;
    if (bx < 1024) {
        const bool isQ = bx < 512;
        const float* src = isQ ? Q : K;
        __nv_bfloat16* hi = isQ ? g_qhi : g_khi;
        __nv_bfloat16* lo = isQ ? g_qlo : g_klo;
        const int base = (bx & 511) * 4096 + tid * 4;
        #pragma unroll
        for (int k = 0; k < 4; k++) {
            int i = base + k * 1024;
            float4 x = *(const float4*)(src + i);
            __nv_bfloat162 h0 = __float22bfloat162_rn(make_float2(x.x, x.y));
            __nv_bfloat162 h1 = __float22bfloat162_rn(make_float2(x.z, x.w));
            *(__nv_bfloat162*)(hi + i) = h0;
            *(__nv_bfloat162*)(hi + i + 2) = h1;
            __nv_bfloat162 l0 = __float22bfloat162_rn(make_float2(
                x.x - __bfloat162float(h0.x), x.y - __bfloat162float(h0.y)));
            __nv_bfloat162 l1 = __float22bfloat162_rn(make_float2(
                x.z - __bfloat162float(h1.x), x.w - __bfloat162float(h1.y)));
            *(__nv_bfloat162*)(lo + i) = l0;
            *(__nv_bfloat162*)(lo + i + 2) = l1;
        }
    } else if (bx < 3072) {
        const int v = bx - 1024;
        const int b = v >> 7, s0 = (v & 63) * 32, d0 = ((v >> 6) & 1) * 32;
        const int tx = tid & 31, ty = tid >> 5;
        const float* ip = V + (size_t)b * SEQ * DKE;
        for (int i = ty; i < 32; i += 8) tile[i][tx] = ip[(size_t)(s0 + i) * DKE + d0 + tx];
        __syncthreads();
        for (int i = ty; i < 32; i += 8) {
            float x = tile[tx][i];
            __nv_bfloat16 h = __float2bfloat16(x);
            size_t oi = ((size_t)b * DKE + d0 + i) * SEQ + s0 + tx;
            g_vthi[oi] = h;
            g_vtlo[oi] = __float2bfloat16(x - __bfloat162float(h));
        }
    } else {
        const int r = bx - 3072;
        const int c0 = (r % 68) * 32, d0 = (r / 68) * 32;
        const int tx = tid & 31, ty = tid >> 5;
        for (int i = ty; i < 32; i += 8) {
            int c = c0 + tx;
            tile[i][tx] = (c < SEQ) ? Kr[(size_t)(d0 + i) * SEQ + c] : 0.0f;
        }
        __syncthreads();
        for (int i = ty; i < 32; i += 8)
            g_krthi[(size_t)(c0 + i) * DKE + d0 + tx] = __float2bfloat16(tile[tx][i]);
    }
}

// -------- smem layout (bytes) --------
#define KHI_O 0            /* 128 rows x 144B */
#define KLO_O 18432
#define KR_O  36864        /* 256 rows x 144B */
#define VHI_O 73728        /* 64 rows x 272B */
#define VLO_O 91136
#define BS_O  108544       /* bf16 128 x 136 (272B stride) */
#define PHI_O 143360       /* bf16 128 x 136 */
#define PLO_O 178176       /* bf16 128 x 136 */
#define SMEM_TOTAL 212992

__global__ __launch_bounds__(256, 1)
void attn_mma_kernel(float* __restrict__ out) {
    extern __shared__ char smem[];
    const uint32_t sm = smem_to_u32(smem);
    const int tid = threadIdx.x, w = tid >> 5, l = tid & 31;
    const int g = l >> 2, tg = l & 3;
    const int R = w * 16;
    const int ua = R + g, ub = R + g + 8;
    const int b = blockIdx.y;
    const int u0 = (15 - (int)blockIdx.x) * 128;  // big tiles first

    // ---- stage Q hi/lo into K buffers, build persistent Q fragments ----
    for (int i = tid; i < 1024; i += 256) {
        int r = i >> 3, c = i & 7;
        CP16(sm + KHI_O + r * 144 + c * 16,
             (const char*)(g_qhi + ((size_t)b * SEQ + u0 + r) * DKE + c * 8));
        CP16(sm + KLO_O + r * 144 + c * 16,
             (const char*)(g_qlo + ((size_t)b * SEQ + u0 + r) * DKE + c * 8));
    }
    CP_COMMIT();
    CP_WAIT0();
    __syncthreads();

    uint32_t qh[4][4], ql[4][4];
    {
        const int qrow = R + (l & 15);
        const int qko = ((l >> 4) & 1) * 8;
        #pragma unroll
        for (int c = 0; c < 4; c++) {
            uint32_t off = (uint32_t)(qrow * 144 + (c * 16 + qko) * 2);
            LDSM4(qh[c][0], qh[c][1], qh[c][2], qh[c][3], sm + KHI_O + off);
            LDSM4(ql[c][0], ql[c][1], ql[c][2], ql[c][3], sm + KLO_O + off);
        }
    }

    const int brow = l & 7;
    const int bko = (l >> 3) * 8;
    // P A-fragment ldmatrix lane address (row within warp tile, 272B stride)
    const uint32_t parow = (uint32_t)((R + (l & 15)) * 272 + ((l >> 4) & 1) * 16);

    float m_a = -1e30f, m_b = -1e30f, l_a = 0.0f, l_b = 0.0f;
    float o[8][4];
    #pragma unroll
    for (int j = 0; j < 8; j++) { o[j][0] = o[j][1] = o[j][2] = o[j][3] = 0.0f; }

    const int nIter = u0 / 128 + 1;
    for (int it = 0; it < nIter; ++it) {
        const int t0 = it * 128;
        const int c_base = 1920 - u0 + t0;
        __syncthreads();  // previous tiles fully consumed (also covers Q extract on it=0)

        // ---- stage K, Kr, V tiles ----
        for (int i = tid; i < 1024; i += 256) {
            int r = i >> 3, c = i & 7;
            CP16(sm + KHI_O + r * 144 + c * 16,
                 (const char*)(g_khi + ((size_t)b * SEQ + t0 + r) * DKE + c * 8));
            CP16(sm + KLO_O + r * 144 + c * 16,
                 (const char*)(g_klo + ((size_t)b * SEQ + t0 + r) * DKE + c * 8));
        }
        for (int i = tid; i < 2048; i += 256) {
            int r = i >> 3, c = i & 7;
            CP16(sm + KR_O + r * 144 + c * 16,
                 (const char*)(g_krthi + (size_t)(c_base + r) * DKE + c * 8));
        }
        for (int i = tid; i < 1024; i += 256) {
            int d = i >> 4, c = i & 15;
            size_t src = ((size_t)b * DKE + d) * SEQ + t0 + c * 8;
            CP16(sm + VHI_O + d * 272 + c * 16, (const char*)(g_vthi + src));
            CP16(sm + VLO_O + d * 272 + c * 16, (const char*)(g_vtlo + src));
        }
        CP_COMMIT();
        CP_WAIT0();
        __syncthreads();

        // ---- S = Q K^T, 3 error-compensated passes ----
        float s[16][4];
        #pragma unroll
        for (int j = 0; j < 16; j++) {
            uint32_t bh[8], bl[8];
            uint32_t ab = (uint32_t)((8 * j + brow) * 144 + bko * 2);
            LDSM4(bh[0], bh[1], bh[2], bh[3], sm + KHI_O + ab);
            LDSM4(bh[4], bh[5], bh[6], bh[7], sm + KHI_O + ab + 64);
            LDSM4(bl[0], bl[1], bl[2], bl[3], sm + KLO_O + ab);
            LDSM4(bl[4], bl[5], bl[6], bl[7], sm + KLO_O + ab + 64);
            float* d = s[j];
            d[0] = d[1] = d[2] = d[3] = 0.0f;
            #pragma unroll
            for (int c = 0; c < 4; c++) {
                MMA16816(d, qh[c], bh[2 * c], bh[2 * c + 1]);
                MMA16816(d, qh[c], bl[2 * c], bl[2 * c + 1]);
                MMA16816(d, ql[c], bh[2 * c], bh[2 * c + 1]);
            }
        }

        // ---- bias GEMM (Qhi only) on this warp's 18 window tiles + shift scatter (bf16) ----
        {
            __nv_bfloat16* Bs = (__nv_bfloat16*)(smem + BS_O);
            const int j0 = 14 - 2 * w;
            #pragma unroll
            for (int jj = 0; jj < 18; jj++) {
                int j = j0 + jj;
                uint32_t kb[8];
                uint32_t ab = (uint32_t)((8 * j + brow) * 144 + bko * 2);
                LDSM4(kb[0], kb[1], kb[2], kb[3], sm + KR_O + ab);
                LDSM4(kb[4], kb[5], kb[6], kb[7], sm + KR_O + ab + 64);
                float d[4] = {0.0f, 0.0f, 0.0f, 0.0f};
                #pragma unroll
                for (int c = 0; c < 4; c++)
                    MMA16816(d, qh[c], kb[2 * c], kb[2 * c + 1]);
                int cc = 8 * j + 2 * tg;
                int ta = cc + ua - 127, tb = cc + ub - 127;
                if ((unsigned)ta < 128u)       Bs[ua * 136 + ta] = __float2bfloat16(d[0]);
                if ((unsigned)(ta + 1) < 128u) Bs[ua * 136 + ta + 1] = __float2bfloat16(d[1]);
                if ((unsigned)tb < 128u)       Bs[ub * 136 + tb] = __float2bfloat16(d[2]);
                if ((unsigned)(tb + 1) < 128u) Bs[ub * 136 + tb + 1] = __float2bfloat16(d[3]);
            }
            __syncwarp();
        }

        // ---- logits + online softmax ----
        {
            const __nv_bfloat16* Bs = (const __nv_bfloat16*)(smem + BS_O);
            #pragma unroll
            for (int j = 0; j < 16; j++) {
                int cc = 8 * j + 2 * tg;
                __nv_bfloat162 ba = *(__nv_bfloat162*)&Bs[ua * 136 + cc];
                __nv_bfloat162 bb = *(__nv_bfloat162*)&Bs[ub * 136 + cc];
                s[j][0] = (s[j][0] + __bfloat162float(ba.x)) * C_SCALE;
                s[j][1] = (s[j][1] + __bfloat162float(ba.y)) * C_SCALE;
                s[j][2] = (s[j][2] + __bfloat162float(bb.x)) * C_SCALE;
                s[j][3] = (s[j][3] + __bfloat162float(bb.y)) * C_SCALE;
            }
        }
        if (t0 == u0) {
            #pragma unroll
            for (int j = 0; j < 16; j++) {
                int cc = 8 * j + 2 * tg;
                if (cc > ua)     s[j][0] = -1e30f;
                if (cc + 1 > ua) s[j][1] = -1e30f;
                if (cc > ub)     s[j][2] = -1e30f;
                if (cc + 1 > ub) s[j][3] = -1e30f;
            }
        }
        float ma = -1e30f, mb = -1e30f;
        #pragma unroll
        for (int j = 0; j < 16; j++) {
            ma = fmaxf(ma, fmaxf(s[j][0], s[j][1]));
            mb = fmaxf(mb, fmaxf(s[j][2], s[j][3]));
        }
        ma = fmaxf(ma, __shfl_xor_sync(0xffffffffu, ma, 1));
        ma = fmaxf(ma, __shfl_xor_sync(0xffffffffu, ma, 2));
        mb = fmaxf(mb, __shfl_xor_sync(0xffffffffu, mb, 1));
        mb = fmaxf(mb, __shfl_xor_sync(0xffffffffu, mb, 2));
        const float mna = fmaxf(m_a, ma), mnb = fmaxf(m_b, mb);
        const float alfa = fexp2(m_a - mna), alfb = fexp2(m_b - mnb);
        m_a = mna; m_b = mnb;
        float pa = 0.0f, pb = 0.0f;
        {
            __nv_bfloat16* Ph = (__nv_bfloat16*)(smem + PHI_O);
            __nv_bfloat16* Pl = (__nv_bfloat16*)(smem + PLO_O);
            #pragma unroll
            for (int j = 0; j < 16; j++) {
                int cc = 8 * j + 2 * tg;
                float p0 = fexp2(s[j][0] - mna);
                float p1 = fexp2(s[j][1] - mna);
                float p2 = fexp2(s[j][2] - mnb);
                float p3 = fexp2(s[j][3] - mnb);
                pa += p0 + p1;
                pb += p2 + p3;
                __nv_bfloat162 h0 = __float22bfloat162_rn(make_float2(p0, p1));
                __nv_bfloat162 h1 = __float22bfloat162_rn(make_float2(p2, p3));
                __nv_bfloat162 l0 = __float22bfloat162_rn(make_float2(
                    p0 - __bfloat162float(h0.x), p1 - __bfloat162float(h0.y)));
                __nv_bfloat162 l1 = __float22bfloat162_rn(make_float2(
                    p2 - __bfloat162float(h1.x), p3 - __bfloat162float(h1.y)));
                *(__nv_bfloat162*)&Ph[ua * 136 + cc] = h0;
                *(__nv_bfloat162*)&Ph[ub * 136 + cc] = h1;
                *(__nv_bfloat162*)&Pl[ua * 136 + cc] = l0;
                *(__nv_bfloat162*)&Pl[ub * 136 + cc] = l1;
            }
            __syncwarp();
        }
        pa += __shfl_xor_sync(0xffffffffu, pa, 1);
        pa += __shfl_xor_sync(0xffffffffu, pa, 2);
        pb += __shfl_xor_sync(0xffffffffu, pb, 1);
        pb += __shfl_xor_sync(0xffffffffu, pb, 2);
        l_a = l_a * alfa + pa;
        l_b = l_b * alfb + pb;
        #pragma unroll
        for (int j = 0; j < 8; j++) {
            o[j][0] *= alfa; o[j][1] *= alfa;
            o[j][2] *= alfb; o[j][3] *= alfb;
        }

        // ---- O += P V: outer k-chunk (32 wide), A-frags from smem ----
        #pragma unroll
        for (int cp = 0; cp < 4; cp++) {
            uint32_t ah[8], al[8];
            uint32_t pa0 = parow + (uint32_t)(cp * 64);          // k-tile 2cp
            LDSM4(ah[0], ah[1], ah[2], ah[3], sm + PHI_O + pa0);
            LDSM4(ah[4], ah[5], ah[6], ah[7], sm + PHI_O + pa0 + 32);
            LDSM4(al[0], al[1], al[2], al[3], sm + PLO_O + pa0);
            LDSM4(al[4], al[5], al[6], al[7], sm + PLO_O + pa0 + 32);
            #pragma unroll
            for (int jd = 0; jd < 8; jd++) {
                uint32_t vh[4], vl[4];
                uint32_t vb = (uint32_t)((8 * jd + brow) * 272 + bko * 2 + cp * 64);
                LDSM4(vh[0], vh[1], vh[2], vh[3], sm + VHI_O + vb);
                LDSM4(vl[0], vl[1], vl[2], vl[3], sm + VLO_O + vb);
                float* d = o[jd];
                MMA16816(d, (ah + 0), vh[0], vh[1]);
                MMA16816(d, (ah + 0), vl[0], vl[1]);
                MMA16816(d, (al + 0), vh[0], vh[1]);
                MMA16816(d, (ah + 4), vh[2], vh[3]);
                MMA16816(d, (ah + 4), vl[2], vl[3]);
                MMA16816(d, (al + 4), vh[2], vh[3]);
            }
        }
    }

    // ---- epilogue ----
    const float inva = 1.0f / l_a, invb = 1.0f / l_b;
    float* orow_a = out + ((size_t)b * SEQ + u0 + ua) * DKE;
    float* orow_b = out + ((size_t)b * SEQ + u0 + ub) * DKE;
    #pragma unroll
    for (int jd = 0; jd < 8; jd++) {
        int cc = 8 * jd + 2 * tg;
        float2 ra, rb;
        ra.x = o[jd][0] * inva; ra.y = o[jd][1] * inva;
        rb.x = o[jd][2] * invb; rb.y = o[jd][3] * invb;
        *(float2*)(orow_a + cc) = ra;
        *(float2*)(orow_b + cc) = rb;
    }
}

extern "C" void kernel_launch(void* const* d_in, const int* in_sizes, int n_in,
                              void* d_out, int out_size) {
    const float* Q  = (const float*)d_in[0];
    const float* K  = (const float*)d_in[1];
    const float* V  = (const float*)d_in[2];
    const float* Kr = (const float*)d_in[3];
    float* out = (float*)d_out;

    cudaFuncSetAttribute(attn_mma_kernel, cudaFuncAttributeMaxDynamicSharedMemorySize, SMEM_TOTAL);

    prologue_kernel<<<3208, 256>>>(Q, K, V, Kr);
    attn_mma_kernel<<<dim3(16, BSZ), 256, SMEM_TOTAL>>>(out);
}

// round 10
// speedup vs baseline: 1.0256x; 1.0256x over previous
#include <cuda_runtime.h>
#include <cuda_bf16.h>
#include <cstdint>

#define BSZ 16
#define SEQ 2048
#define DKE 64
#define KR_ROWS 2176

// -------- device-global bf16 split scratch --------
__device__ __align__(16) __nv_bfloat16 g_qhi[BSZ * SEQ * DKE];
__device__ __align__(16) __nv_bfloat16 g_qlo[BSZ * SEQ * DKE];
__device__ __align__(16) __nv_bfloat16 g_khi[BSZ * SEQ * DKE];
__device__ __align__(16) __nv_bfloat16 g_klo[BSZ * SEQ * DKE];
__device__ __align__(16) __nv_bfloat16 g_vthi[BSZ * DKE * SEQ];  // [b][d][t]
__device__ __align__(16) __nv_bfloat16 g_vtlo[BSZ * DKE * SEQ];
__device__ __align__(16) __nv_bfloat16 g_krthi[KR_ROWS * DKE];   // [c][d], c>=SEQ zero

__device__ __forceinline__ uint32_t smem_to_u32(const void* p) {
    uint32_t a;
    asm("{ .reg .u64 t; cvta.to.shared.u64 t, %1; cvt.u32.u64 %0, t; }" : "=r"(a) : "l"(p));
    return a;
}

#define LDSM4(r0, r1, r2, r3, addr) \
    asm volatile("ldmatrix.sync.aligned.m8n8.x4.shared.b16 {%0,%1,%2,%3}, [%4];" \
                 : "=r"(r0), "=r"(r1), "=r"(r2), "=r"(r3) : "r"(addr))

#define MMA16816(d, a, bb0, bb1) \
    asm volatile("mma.sync.aligned.m16n8k16.row.col.f32.bf16.bf16.f32 " \
                 "{%0,%1,%2,%3},{%4,%5,%6,%7},{%8,%9},{%0,%1,%2,%3};" \
                 : "+f"((d)[0]), "+f"((d)[1]), "+f"((d)[2]), "+f"((d)[3]) \
                 : "r"((a)[0]), "r"((a)[1]), "r"((a)[2]), "r"((a)[3]), "r"(bb0), "r"(bb1))

#define CP16(dst, src) \
    asm volatile("cp.async.ca.shared.global [%0], [%1], 16;" :: "r"(dst), "l"(src))
#define CP_COMMIT() asm volatile("cp.async.commit_group;")
#define CP_WAIT0()  asm volatile("cp.async.wait_group 0;")
#define PAIR_BAR(id) asm volatile("bar.sync %0, 64;" :: "r"(id) : "memory")

#define C_SCALE 0.1803368801111204f  /* log2(e)/sqrt(64) */

__device__ __forceinline__ float fexp2(float x) {
    x = fmaxf(x, -126.0f);
    float n = rintf(x), f = x - n;
    float r = 0.00133335581464f;
    r = fmaf(r, f, 0.00961812910763f);
    r = fmaf(r, f, 0.0555041086648f);
    r = fmaf(r, f, 0.2402265069591f);
    r = fmaf(r, f, 0.69314718056f);
    r = fmaf(r, f, 1.0f);
    return r * __int_as_float(((int)n + 127) << 23);
}

// -------- merged prologue: 3208 blocks x 256 threads --------
__global__ void prologue_kernel(const float* __restrict__ Q, const float* __restrict__ K,
                                const float* __restrict__ V, const float* __restrict__ Kr) {
    __shared__ float tile[32][33];
    const int bx = blockIdx.x, tid = threadIdx.x;
    if (bx < 1024) {
        const bool isQ = bx < 512;
        const float* src = isQ ? Q : K;
        __nv_bfloat16* hi = isQ ? g_qhi : g_khi;
        __nv_bfloat16* lo = isQ ? g_qlo : g_klo;
        const int base = (bx & 511) * 4096 + tid * 4;
        #pragma unroll
        for (int k = 0; k < 4; k++) {
            int i = base + k * 1024;
            float4 x = *(const float4*)(src + i);
            __nv_bfloat162 h0 = __float22bfloat162_rn(make_float2(x.x, x.y));
            __nv_bfloat162 h1 = __float22bfloat162_rn(make_float2(x.z, x.w));
            *(__nv_bfloat162*)(hi + i) = h0;
            *(__nv_bfloat162*)(hi + i + 2) = h1;
            __nv_bfloat162 l0 = __float22bfloat162_rn(make_float2(
                x.x - __bfloat162float(h0.x), x.y - __bfloat162float(h0.y)));
            __nv_bfloat162 l1 = __float22bfloat162_rn(make_float2(
                x.z - __bfloat162float(h1.x), x.w - __bfloat162float(h1.y)));
            *(__nv_bfloat162*)(lo + i) = l0;
            *(__nv_bfloat162*)(lo + i + 2) = l1;
        }
    } else if (bx < 3072) {
        const int v = bx - 1024;
        const int b = v >> 7, s0 = (v & 63) * 32, d0 = ((v >> 6) & 1) * 32;
        const int tx = tid & 31, ty = tid >> 5;
        const float* ip = V + (size_t)b * SEQ * DKE;
        for (int i = ty; i < 32; i += 8) tile[i][tx] = ip[(size_t)(s0 + i) * DKE + d0 + tx];
        __syncthreads();
        for (int i = ty; i < 32; i += 8) {
            float x = tile[tx][i];
            __nv_bfloat16 h = __float2bfloat16(x);
            size_t oi = ((size_t)b * DKE + d0 + i) * SEQ + s0 + tx;
            g_vthi[oi] = h;
            g_vtlo[oi] = __float2bfloat16(x - __bfloat162float(h));
        }
    } else {
        const int r = bx - 3072;
        const int c0 = (r % 68) * 32, d0 = (r / 68) * 32;
        const int tx = tid & 31, ty = tid >> 5;
        for (int i = ty; i < 32; i += 8) {
            int c = c0 + tx;
            tile[i][tx] = (c < SEQ) ? Kr[(size_t)(d0 + i) * SEQ + c] : 0.0f;
        }
        __syncthreads();
        for (int i = ty; i < 32; i += 8)
            g_krthi[(size_t)(c0 + i) * DKE + d0 + tx] = __float2bfloat16(tile[tx][i]);
    }
}

// -------- smem layout (bytes) --------
#define KHI_O 0            /* 128 rows x 144B (row=t, col=k) */
#define KLO_O 18432
#define KR_O  36864        /* 256 rows x 144B */
#define VHI_O 73728        /* 64 rows x 272B (row=d, col=t) */
#define VLO_O 91136
#define BS_O  108544       /* bf16 128 x 136 (272B stride) */
#define PHI_O 143360       /* bf16 128 x 136 */
#define PLO_O 178176       /* bf16 128 x 136 */
#define RED_O 212992       /* f32: [0..255] max, [256..511] sum (row*2+half) */
#define SMEM_TOTAL 215040

__global__ __launch_bounds__(512, 1)
void attn_mma_kernel(float* __restrict__ out) {
    extern __shared__ char smem[];
    const uint32_t sm = smem_to_u32(smem);
    const int tid = threadIdx.x, w = tid >> 5, l = tid & 31;
    const int g = l >> 2, tg = l & 3;
    const int ws = w & 7;          // row strip
    const int h = w >> 3;          // column half (t for S, d for PV)
    const int Rb = ws * 16;
    const int ua = Rb + g, ub = Rb + g + 8;
    const int bar_id = 1 + ws;     // named pair barrier (warps ws, ws+8)
    const int b = blockIdx.y;
    const int u0 = (15 - (int)blockIdx.x) * 128;  // big tiles first

    // ---- stage Q hi/lo into K buffers, build persistent Q fragments ----
    for (int i = tid; i < 1024; i += 512) {
        int r = i >> 3, c = i & 7;
        CP16(sm + KHI_O + r * 144 + c * 16,
             (const char*)(g_qhi + ((size_t)b * SEQ + u0 + r) * DKE + c * 8));
        CP16(sm + KLO_O + r * 144 + c * 16,
             (const char*)(g_qlo + ((size_t)b * SEQ + u0 + r) * DKE + c * 8));
    }
    CP_COMMIT();
    CP_WAIT0();
    __syncthreads();

    uint32_t qh[4][4], ql[4][4];
    {
        const int qrow = Rb + (l & 15);
        const int qko = ((l >> 4) & 1) * 8;
        #pragma unroll
        for (int c = 0; c < 4; c++) {
            uint32_t off = (uint32_t)(qrow * 144 + (c * 16 + qko) * 2);
            LDSM4(qh[c][0], qh[c][1], qh[c][2], qh[c][3], sm + KHI_O + off);
            LDSM4(ql[c][0], ql[c][1], ql[c][2], ql[c][3], sm + KLO_O + off);
        }
    }

    const int brow = l & 7;
    const int bko = (l >> 3) * 8;
    const uint32_t parow = (uint32_t)((Rb + (l & 15)) * 272 + ((l >> 4) & 1) * 16);
    float* red = (float*)(smem + RED_O);

    float m_a = -1e30f, m_b = -1e30f, l_a = 0.0f, l_b = 0.0f;
    float o[4][4];
    #pragma unroll
    for (int j = 0; j < 4; j++) { o[j][0] = o[j][1] = o[j][2] = o[j][3] = 0.0f; }

    const int nIter = u0 / 128 + 1;
    for (int it = 0; it < nIter; ++it) {
        const int t0 = it * 128;
        const int c_base = 1920 - u0 + t0;
        __syncthreads();  // previous tiles fully consumed (also covers Q extract on it=0)

        // ---- stage K, Kr, V tiles ----
        for (int i = tid; i < 1024; i += 512) {
            int r = i >> 3, c = i & 7;
            CP16(sm + KHI_O + r * 144 + c * 16,
                 (const char*)(g_khi + ((size_t)b * SEQ + t0 + r) * DKE + c * 8));
            CP16(sm + KLO_O + r * 144 + c * 16,
                 (const char*)(g_klo + ((size_t)b * SEQ + t0 + r) * DKE + c * 8));
        }
        for (int i = tid; i < 2048; i += 512) {
            int r = i >> 3, c = i & 7;
            CP16(sm + KR_O + r * 144 + c * 16,
                 (const char*)(g_krthi + (size_t)(c_base + r) * DKE + c * 8));
        }
        for (int i = tid; i < 1024; i += 512) {
            int d = i >> 4, c = i & 15;
            size_t src = ((size_t)b * DKE + d) * SEQ + t0 + c * 8;
            CP16(sm + VHI_O + d * 272 + c * 16, (const char*)(g_vthi + src));
            CP16(sm + VLO_O + d * 272 + c * 16, (const char*)(g_vtlo + src));
        }
        CP_COMMIT();
        CP_WAIT0();
        __syncthreads();

        // ---- S = Q K^T (this warp: 16 rows x 64 t-cols), 3 passes ----
        float s[8][4];
        #pragma unroll
        for (int j = 0; j < 8; j++) {
            uint32_t bh[8], bl[8];
            uint32_t ab = (uint32_t)((8 * (8 * h + j) + brow) * 144 + bko * 2);
            LDSM4(bh[0], bh[1], bh[2], bh[3], sm + KHI_O + ab);
            LDSM4(bh[4], bh[5], bh[6], bh[7], sm + KHI_O + ab + 64);
            LDSM4(bl[0], bl[1], bl[2], bl[3], sm + KLO_O + ab);
            LDSM4(bl[4], bl[5], bl[6], bl[7], sm + KLO_O + ab + 64);
            float* d = s[j];
            d[0] = d[1] = d[2] = d[3] = 0.0f;
            #pragma unroll
            for (int c = 0; c < 4; c++) {
                MMA16816(d, qh[c], bh[2 * c], bh[2 * c + 1]);
                MMA16816(d, qh[c], bl[2 * c], bl[2 * c + 1]);
                MMA16816(d, ql[c], bh[2 * c], bh[2 * c + 1]);
            }
        }

        // ---- bias GEMM (Qhi only): pair's 18 window tiles split 9/9 ----
        {
            __nv_bfloat16* Bs = (__nv_bfloat16*)(smem + BS_O);
            const int j0 = 14 - 2 * ws + 9 * h;
            #pragma unroll
            for (int jj = 0; jj < 9; jj++) {
                int j = j0 + jj;
                uint32_t kb[8];
                uint32_t ab = (uint32_t)((8 * j + brow) * 144 + bko * 2);
                LDSM4(kb[0], kb[1], kb[2], kb[3], sm + KR_O + ab);
                LDSM4(kb[4], kb[5], kb[6], kb[7], sm + KR_O + ab + 64);
                float d[4] = {0.0f, 0.0f, 0.0f, 0.0f};
                #pragma unroll
                for (int c = 0; c < 4; c++)
                    MMA16816(d, qh[c], kb[2 * c], kb[2 * c + 1]);
                int cc = 8 * j + 2 * tg;
                int ta = cc + ua - 127, tb = cc + ub - 127;
                if ((unsigned)ta < 128u)       Bs[ua * 136 + ta] = __float2bfloat16(d[0]);
                if ((unsigned)(ta + 1) < 128u) Bs[ua * 136 + ta + 1] = __float2bfloat16(d[1]);
                if ((unsigned)tb < 128u)       Bs[ub * 136 + tb] = __float2bfloat16(d[2]);
                if ((unsigned)(tb + 1) < 128u) Bs[ub * 136 + tb + 1] = __float2bfloat16(d[3]);
            }
        }
        PAIR_BAR(bar_id);  // both halves' bias scatter visible

        // ---- logits + causal mask ----
        {
            const __nv_bfloat16* Bs = (const __nv_bfloat16*)(smem + BS_O);
            #pragma unroll
            for (int j = 0; j < 8; j++) {
                int cc = 64 * h + 8 * j + 2 * tg;
                __nv_bfloat162 ba = *(__nv_bfloat162*)&Bs[ua * 136 + cc];
                __nv_bfloat162 bb = *(__nv_bfloat162*)&Bs[ub * 136 + cc];
                s[j][0] = (s[j][0] + __bfloat162float(ba.x)) * C_SCALE;
                s[j][1] = (s[j][1] + __bfloat162float(ba.y)) * C_SCALE;
                s[j][2] = (s[j][2] + __bfloat162float(bb.x)) * C_SCALE;
                s[j][3] = (s[j][3] + __bfloat162float(bb.y)) * C_SCALE;
            }
        }
        if (t0 == u0) {
            #pragma unroll
            for (int j = 0; j < 8; j++) {
                int cc = 64 * h + 8 * j + 2 * tg;
                if (cc > ua)     s[j][0] = -1e30f;
                if (cc + 1 > ua) s[j][1] = -1e30f;
                if (cc > ub)     s[j][2] = -1e30f;
                if (cc + 1 > ub) s[j][3] = -1e30f;
            }
        }

        // ---- partial row max over this half ----
        float ma = -1e30f, mb = -1e30f;
        #pragma unroll
        for (int j = 0; j < 8; j++) {
            ma = fmaxf(ma, fmaxf(s[j][0], s[j][1]));
            mb = fmaxf(mb, fmaxf(s[j][2], s[j][3]));
        }
        ma = fmaxf(ma, __shfl_xor_sync(0xffffffffu, ma, 1));
        ma = fmaxf(ma, __shfl_xor_sync(0xffffffffu, ma, 2));
        mb = fmaxf(mb, __shfl_xor_sync(0xffffffffu, mb, 1));
        mb = fmaxf(mb, __shfl_xor_sync(0xffffffffu, mb, 2));
        if (tg == 0) { red[ua * 2 + h] = ma; red[ub * 2 + h] = mb; }
        PAIR_BAR(bar_id);
        const float mna = fmaxf(m_a, fmaxf(red[ua * 2], red[ua * 2 + 1]));
        const float mnb = fmaxf(m_b, fmaxf(red[ub * 2], red[ub * 2 + 1]));
        const float alfa = fexp2(m_a - mna), alfb = fexp2(m_b - mnb);
        m_a = mna; m_b = mnb;

        // ---- exp, partial sums, P hi/lo to smem ----
        float pa = 0.0f, pb = 0.0f;
        {
            __nv_bfloat16* Ph = (__nv_bfloat16*)(smem + PHI_O);
            __nv_bfloat16* Pl = (__nv_bfloat16*)(smem + PLO_O);
            #pragma unroll
            for (int j = 0; j < 8; j++) {
                int cc = 64 * h + 8 * j + 2 * tg;
                float p0 = fexp2(s[j][0] - mna);
                float p1 = fexp2(s[j][1] - mna);
                float p2 = fexp2(s[j][2] - mnb);
                float p3 = fexp2(s[j][3] - mnb);
                pa += p0 + p1;
                pb += p2 + p3;
                __nv_bfloat162 h0 = __float22bfloat162_rn(make_float2(p0, p1));
                __nv_bfloat162 h1 = __float22bfloat162_rn(make_float2(p2, p3));
                __nv_bfloat162 l0 = __float22bfloat162_rn(make_float2(
                    p0 - __bfloat162float(h0.x), p1 - __bfloat162float(h0.y)));
                __nv_bfloat162 l1 = __float22bfloat162_rn(make_float2(
                    p2 - __bfloat162float(h1.x), p3 - __bfloat162float(h1.y)));
                *(__nv_bfloat162*)&Ph[ua * 136 + cc] = h0;
                *(__nv_bfloat162*)&Ph[ub * 136 + cc] = h1;
                *(__nv_bfloat162*)&Pl[ua * 136 + cc] = l0;
                *(__nv_bfloat162*)&Pl[ub * 136 + cc] = l1;
            }
        }
        pa += __shfl_xor_sync(0xffffffffu, pa, 1);
        pa += __shfl_xor_sync(0xffffffffu, pa, 2);
        pb += __shfl_xor_sync(0xffffffffu, pb, 1);
        pb += __shfl_xor_sync(0xffffffffu, pb, 2);
        if (tg == 0) { red[256 + ua * 2 + h] = pa; red[256 + ub * 2 + h] = pb; }
        PAIR_BAR(bar_id);  // P tiles + sums visible to both halves
        l_a = l_a * alfa + red[256 + ua * 2] + red[256 + ua * 2 + 1];
        l_b = l_b * alfb + red[256 + ub * 2] + red[256 + ub * 2 + 1];
        #pragma unroll
        for (int j = 0; j < 4; j++) {
            o[j][0] *= alfa; o[j][1] *= alfa;
            o[j][2] *= alfb; o[j][3] *= alfb;
        }

        // ---- O += P V (this warp: 16 rows x 32 d-cols), 3 passes ----
        #pragma unroll
        for (int cp = 0; cp < 4; cp++) {
            uint32_t ah[8], al[8];
            uint32_t pa0 = parow + (uint32_t)(cp * 64);
            LDSM4(ah[0], ah[1], ah[2], ah[3], sm + PHI_O + pa0);
            LDSM4(ah[4], ah[5], ah[6], ah[7], sm + PHI_O + pa0 + 32);
            LDSM4(al[0], al[1], al[2], al[3], sm + PLO_O + pa0);
            LDSM4(al[4], al[5], al[6], al[7], sm + PLO_O + pa0 + 32);
            #pragma unroll
            for (int jd = 0; jd < 4; jd++) {
                uint32_t vh[4], vl[4];
                uint32_t vb = (uint32_t)((8 * (4 * h + jd) + brow) * 272 + bko * 2 + cp * 64);
                LDSM4(vh[0], vh[1], vh[2], vh[3], sm + VHI_O + vb);
                LDSM4(vl[0], vl[1], vl[2], vl[3], sm + VLO_O + vb);
                float* d = o[jd];
                MMA16816(d, (ah + 0), vh[0], vh[1]);
                MMA16816(d, (ah + 0), vl[0], vl[1]);
                MMA16816(d, (al + 0), vh[0], vh[1]);
                MMA16816(d, (ah + 4), vh[2], vh[3]);
                MMA16816(d, (ah + 4), vl[2], vl[3]);
                MMA16816(d, (al + 4), vh[2], vh[3]);
            }
        }
    }

    // ---- epilogue ----
    const float inva = 1.0f / l_a, invb = 1.0f / l_b;
    float* orow_a = out + ((size_t)b * SEQ + u0 + ua) * DKE + 32 * h;
    float* orow_b = out + ((size_t)b * SEQ + u0 + ub) * DKE + 32 * h;
    #pragma unroll
    for (int jd = 0; jd < 4; jd++) {
        int cc = 8 * jd + 2 * tg;
        float2 ra, rb;
        ra.x = o[jd][0] * inva; ra.y = o[jd][1] * inva;
        rb.x = o[jd][2] * invb; rb.y = o[jd][3] * invb;
        *(float2*)(orow_a + cc) = ra;
        *(float2*)(orow_b + cc) = rb;
    }
}

extern "C" void kernel_launch(void* const* d_in, const int* in_sizes, int n_in,
                              void* d_out, int out_size) {
    const float* Q  = (const float*)d_in[0];
    const float* K  = (const float*)d_in[1];
    const float* V  = (const float*)d_in[2];
    const float* Kr = (const float*)d_in[3];
    float* out = (float*)d_out;

    cudaFuncSetAttribute(attn_mma_kernel, cudaFuncAttributeMaxDynamicSharedMemorySize, SMEM_TOTAL);

    prologue_kernel<<<3208, 256>>>(Q, K, V, Kr);
    attn_mma_kernel<<<dim3(16, BSZ), 512, SMEM_TOTAL>>>(out);
}

// round 11
// speedup vs baseline: 1.0451x; 1.0190x over previous
#include <cuda_runtime.h>
#include <cuda_bf16.h>
#include <cstdint>

#define BSZ 16
#define SEQ 2048
#define DKE 64
#define KR_ROWS 2176

// -------- device-global bf16 split scratch --------
__device__ __align__(16) __nv_bfloat16 g_qhi[BSZ * SEQ * DKE];
__device__ __align__(16) __nv_bfloat16 g_qlo[BSZ * SEQ * DKE];
__device__ __align__(16) __nv_bfloat16 g_khi[BSZ * SEQ * DKE];
__device__ __align__(16) __nv_bfloat16 g_klo[BSZ * SEQ * DKE];
__device__ __align__(16) __nv_bfloat16 g_vthi[BSZ * DKE * SEQ];  // [b][d][t]
__device__ __align__(16) __nv_bfloat16 g_vtlo[BSZ * DKE * SEQ];
__device__ __align__(16) __nv_bfloat16 g_krthi[KR_ROWS * DKE];   // [c][d], c>=SEQ zero

__device__ __forceinline__ uint32_t smem_to_u32(const void* p) {
    uint32_t a;
    asm("{ .reg .u64 t; cvta.to.shared.u64 t, %1; cvt.u32.u64 %0, t; }" : "=r"(a) : "l"(p));
    return a;
}

#define LDSM4(r0, r1, r2, r3, addr) \
    asm volatile("ldmatrix.sync.aligned.m8n8.x4.shared.b16 {%0,%1,%2,%3}, [%4];" \
                 : "=r"(r0), "=r"(r1), "=r"(r2), "=r"(r3) : "r"(addr))

#define MMA16816(d, a, bb0, bb1) \
    asm volatile("mma.sync.aligned.m16n8k16.row.col.f32.bf16.bf16.f32 " \
                 "{%0,%1,%2,%3},{%4,%5,%6,%7},{%8,%9},{%0,%1,%2,%3};" \
                 : "+f"((d)[0]), "+f"((d)[1]), "+f"((d)[2]), "+f"((d)[3]) \
                 : "r"((a)[0]), "r"((a)[1]), "r"((a)[2]), "r"((a)[3]), "r"(bb0), "r"(bb1))

#define CP16(dst, src) \
    asm volatile("cp.async.cg.shared.global [%0], [%1], 16;" :: "r"(dst), "l"(src))
#define CP_COMMIT() asm volatile("cp.async.commit_group;")
#define CP_WAIT0()  asm volatile("cp.async.wait_group 0;")
#define PAIR_BAR(id) asm volatile("bar.sync %0, 64;" :: "r"(id) : "memory")

#define C_SCALE 0.1803368801111204f  /* log2(e)/sqrt(64) */

__device__ __forceinline__ float fexp2(float x) {
    x = fmaxf(x, -126.0f);
    float n = rintf(x), f = x - n;
    float r = 0.00133335581464f;
    r = fmaf(r, f, 0.00961812910763f);
    r = fmaf(r, f, 0.0555041086648f);
    r = fmaf(r, f, 0.2402265069591f);
    r = fmaf(r, f, 0.69314718056f);
    r = fmaf(r, f, 1.0f);
    return r * __int_as_float(((int)n + 127) << 23);
}

// -------- merged prologue: 3208 blocks x 256 threads --------
__global__ void prologue_kernel(const float* __restrict__ Q, const float* __restrict__ K,
                                const float* __restrict__ V, const float* __restrict__ Kr) {
    __shared__ float tile[32][33];
    const int bx = blockIdx.x, tid = threadIdx.x;
    if (bx < 1024) {
        const bool isQ = bx < 512;
        const float* src = isQ ? Q : K;
        __nv_bfloat16* hi = isQ ? g_qhi : g_khi;
        __nv_bfloat16* lo = isQ ? g_qlo : g_klo;
        const int base = (bx & 511) * 4096 + tid * 4;
        #pragma unroll
        for (int k = 0; k < 4; k++) {
            int i = base + k * 1024;
            float4 x = *(const float4*)(src + i);
            __nv_bfloat162 h0 = __float22bfloat162_rn(make_float2(x.x, x.y));
            __nv_bfloat162 h1 = __float22bfloat162_rn(make_float2(x.z, x.w));
            *(__nv_bfloat162*)(hi + i) = h0;
            *(__nv_bfloat162*)(hi + i + 2) = h1;
            __nv_bfloat162 l0 = __float22bfloat162_rn(make_float2(
                x.x - __bfloat162float(h0.x), x.y - __bfloat162float(h0.y)));
            __nv_bfloat162 l1 = __float22bfloat162_rn(make_float2(
                x.z - __bfloat162float(h1.x), x.w - __bfloat162float(h1.y)));
            *(__nv_bfloat162*)(lo + i) = l0;
            *(__nv_bfloat162*)(lo + i + 2) = l1;
        }
    } else if (bx < 3072) {
        const int v = bx - 1024;
        const int b = v >> 7, s0 = (v & 63) * 32, d0 = ((v >> 6) & 1) * 32;
        const int tx = tid & 31, ty = tid >> 5;
        const float* ip = V + (size_t)b * SEQ * DKE;
        for (int i = ty; i < 32; i += 8) tile[i][tx] = ip[(size_t)(s0 + i) * DKE + d0 + tx];
        __syncthreads();
        for (int i = ty; i < 32; i += 8) {
            float x = tile[tx][i];
            __nv_bfloat16 h = __float2bfloat16(x);
            size_t oi = ((size_t)b * DKE + d0 + i) * SEQ + s0 + tx;
            g_vthi[oi] = h;
            g_vtlo[oi] = __float2bfloat16(x - __bfloat162float(h));
        }
    } else {
        const int r = bx - 3072;
        const int c0 = (r % 68) * 32, d0 = (r / 68) * 32;
        const int tx = tid & 31, ty = tid >> 5;
        for (int i = ty; i < 32; i += 8) {
            int c = c0 + tx;
            tile[i][tx] = (c < SEQ) ? Kr[(size_t)(d0 + i) * SEQ + c] : 0.0f;
        }
        __syncthreads();
        for (int i = ty; i < 32; i += 8)
            g_krthi[(size_t)(c0 + i) * DKE + d0 + tx] = __float2bfloat16(tile[tx][i]);
    }
}

// -------- smem layout (bytes) --------
#define QHI_O 0            /* 128 rows x 144B, persists whole kernel */
#define QLO_O 18432
#define KHI_O 36864        /* 128 rows x 144B */
#define KLO_O 55296
#define KR_O  73728        /* 256-row ring x 144B */
#define VHI_O 110592       /* 64 rows x 272B */
#define VLO_O 128000
#define BS_O  145408       /* bf16 128 x 136 (272B stride) */
#define SMEM_TOTAL 180224
/* epilogue reuse (dead regions): */
#define XO_O  36864        /* f32 128 rows x 272B (over K tiles) */
#define MX_O  145408       /* f32[128] (over BS) */
#define LX_O  146432       /* f32[128] */

__global__ __launch_bounds__(512, 1)
void attn_mma_kernel(float* __restrict__ out) {
    extern __shared__ char smem[];
    const uint32_t sm = smem_to_u32(smem);
    const int tid = threadIdx.x, w = tid >> 5, l = tid & 31;
    const int g = l >> 2, tg = l & 3;
    const int ws = w & 7;          // row strip
    const int h = w >> 3;          // t-half this warp owns
    const int Rb = ws * 16;
    const int ua = Rb + g, ub = Rb + g + 8;
    const int bar_id = 1 + ws;     // named pair barrier (warps ws, ws+8)
    const int b = blockIdx.y;
    const int u0 = (15 - (int)blockIdx.x) * 128;  // big tiles first
    const int c0 = 1920 - u0;      // Kr window base for it=0

    // ---- kernel prologue staging: Q hi/lo + first KR half ----
    for (int i = tid; i < 1024; i += 512) {
        int r = i >> 3, c = i & 7;
        CP16(sm + QHI_O + r * 144 + c * 16,
             (const char*)(g_qhi + ((size_t)b * SEQ + u0 + r) * DKE + c * 8));
        CP16(sm + QLO_O + r * 144 + c * 16,
             (const char*)(g_qlo + ((size_t)b * SEQ + u0 + r) * DKE + c * 8));
    }
    for (int i = tid; i < 1024; i += 512) {
        int r = i >> 3, c = i & 7;
        CP16(sm + KR_O + r * 144 + c * 16,
             (const char*)(g_krthi + (size_t)(c0 + r) * DKE + c * 8));
    }
    CP_COMMIT();
    CP_WAIT0();
    __syncthreads();

    // persistent Q fragments (Q region never overwritten)
    uint32_t qh[4][4], ql[4][4];
    {
        const int qrow = Rb + (l & 15);
        const int qko = ((l >> 4) & 1) * 8;
        #pragma unroll
        for (int c = 0; c < 4; c++) {
            uint32_t off = (uint32_t)(qrow * 144 + (c * 16 + qko) * 2);
            LDSM4(qh[c][0], qh[c][1], qh[c][2], qh[c][3], sm + QHI_O + off);
            LDSM4(ql[c][0], ql[c][1], ql[c][2], ql[c][3], sm + QLO_O + off);
        }
    }

    const int brow = l & 7;
    const int bko = (l >> 3) * 8;

    float m_a = -1e30f, m_b = -1e30f, l_a = 0.0f, l_b = 0.0f;
    float o[8][4];
    #pragma unroll
    for (int j = 0; j < 8; j++) { o[j][0] = o[j][1] = o[j][2] = o[j][3] = 0.0f; }

    const int nIter = u0 / 128 + 1;
    for (int it = 0; it < nIter; ++it) {
        const int t0 = it * 128;
        __syncthreads();  // previous K/V tiles + dead KR half fully consumed

        // ---- stage K(it), V(it), and this window's new KR half ----
        for (int i = tid; i < 1024; i += 512) {
            int r = i >> 3, c = i & 7;
            CP16(sm + KHI_O + r * 144 + c * 16,
                 (const char*)(g_khi + ((size_t)b * SEQ + t0 + r) * DKE + c * 8));
            CP16(sm + KLO_O + r * 144 + c * 16,
                 (const char*)(g_klo + ((size_t)b * SEQ + t0 + r) * DKE + c * 8));
        }
        {
            const int physbase = 128 * ((it + 1) & 1);     // ring slot for new half
            const int gbase = c0 + 128 * (it + 1);
            for (int i = tid; i < 1024; i += 512) {
                int r = i >> 3, c = i & 7;
                CP16(sm + KR_O + (physbase + r) * 144 + c * 16,
                     (const char*)(g_krthi + (size_t)(gbase + r) * DKE + c * 8));
            }
        }
        for (int i = tid; i < 1024; i += 512) {
            int d = i >> 4, c = i & 15;
            size_t src = ((size_t)b * DKE + d) * SEQ + t0 + c * 8;
            CP16(sm + VHI_O + d * 272 + c * 16, (const char*)(g_vthi + src));
            CP16(sm + VLO_O + d * 272 + c * 16, (const char*)(g_vtlo + src));
        }
        CP_COMMIT();
        CP_WAIT0();
        __syncthreads();

        // ---- S = Q K^T (own 16 rows x own 64 t-cols), 3 passes ----
        float s[8][4];
        #pragma unroll
        for (int j = 0; j < 8; j++) {
            uint32_t bh[8], bl[8];
            uint32_t ab = (uint32_t)((8 * (8 * h + j) + brow) * 144 + bko * 2);
            LDSM4(bh[0], bh[1], bh[2], bh[3], sm + KHI_O + ab);
            LDSM4(bh[4], bh[5], bh[6], bh[7], sm + KHI_O + ab + 64);
            LDSM4(bl[0], bl[1], bl[2], bl[3], sm + KLO_O + ab);
            LDSM4(bl[4], bl[5], bl[6], bl[7], sm + KLO_O + ab + 64);
            float* d = s[j];
            d[0] = d[1] = d[2] = d[3] = 0.0f;
            #pragma unroll
            for (int c = 0; c < 4; c++) {
                MMA16816(d, qh[c], bh[2 * c], bh[2 * c + 1]);
                MMA16816(d, qh[c], bl[2 * c], bl[2 * c + 1]);
                MMA16816(d, ql[c], bh[2 * c], bh[2 * c + 1]);
            }
        }

        // ---- bias GEMM (Qhi only): pair's 18 window tiles split 9/9, ring-indexed ----
        {
            __nv_bfloat16* Bs = (__nv_bfloat16*)(smem + BS_O);
            const int j0 = 14 - 2 * ws + 9 * h;
            #pragma unroll
            for (int jj = 0; jj < 9; jj++) {
                int j = j0 + jj;
                int jp = (j + 16 * it) & 31;   // physical ring tile
                uint32_t kb[8];
                uint32_t ab = (uint32_t)((8 * jp + brow) * 144 + bko * 2);
                LDSM4(kb[0], kb[1], kb[2], kb[3], sm + KR_O + ab);
                LDSM4(kb[4], kb[5], kb[6], kb[7], sm + KR_O + ab + 64);
                float d[4] = {0.0f, 0.0f, 0.0f, 0.0f};
                #pragma unroll
                for (int c = 0; c < 4; c++)
                    MMA16816(d, qh[c], kb[2 * c], kb[2 * c + 1]);
                int cc = 8 * j + 2 * tg;
                int ta = cc + ua - 127, tb = cc + ub - 127;
                if ((unsigned)ta < 128u)       Bs[ua * 136 + ta] = __float2bfloat16(d[0]);
                if ((unsigned)(ta + 1) < 128u) Bs[ua * 136 + ta + 1] = __float2bfloat16(d[1]);
                if ((unsigned)tb < 128u)       Bs[ub * 136 + tb] = __float2bfloat16(d[2]);
                if ((unsigned)(tb + 1) < 128u) Bs[ub * 136 + tb + 1] = __float2bfloat16(d[3]);
            }
        }
        PAIR_BAR(bar_id);  // both halves' bias scatter visible to the pair

        // ---- logits + causal mask (own half) ----
        {
            const __nv_bfloat16* Bs = (const __nv_bfloat16*)(smem + BS_O);
            #pragma unroll
            for (int j = 0; j < 8; j++) {
                int cc = 64 * h + 8 * j + 2 * tg;
                __nv_bfloat162 ba = *(__nv_bfloat162*)&Bs[ua * 136 + cc];
                __nv_bfloat162 bb = *(__nv_bfloat162*)&Bs[ub * 136 + cc];
                s[j][0] = (s[j][0] + __bfloat162float(ba.x)) * C_SCALE;
                s[j][1] = (s[j][1] + __bfloat162float(ba.y)) * C_SCALE;
                s[j][2] = (s[j][2] + __bfloat162float(bb.x)) * C_SCALE;
                s[j][3] = (s[j][3] + __bfloat162float(bb.y)) * C_SCALE;
            }
        }
        if (t0 == u0) {
            #pragma unroll
            for (int j = 0; j < 8; j++) {
                int cc = 64 * h + 8 * j + 2 * tg;
                if (cc > ua)     s[j][0] = -1e30f;
                if (cc + 1 > ua) s[j][1] = -1e30f;
                if (cc > ub)     s[j][2] = -1e30f;
                if (cc + 1 > ub) s[j][3] = -1e30f;
            }
        }

        // ---- warp-local online softmax over own half ----
        float ma = -1e30f, mb = -1e30f;
        #pragma unroll
        for (int j = 0; j < 8; j++) {
            ma = fmaxf(ma, fmaxf(s[j][0], s[j][1]));
            mb = fmaxf(mb, fmaxf(s[j][2], s[j][3]));
        }
        ma = fmaxf(ma, __shfl_xor_sync(0xffffffffu, ma, 1));
        ma = fmaxf(ma, __shfl_xor_sync(0xffffffffu, ma, 2));
        mb = fmaxf(mb, __shfl_xor_sync(0xffffffffu, mb, 1));
        mb = fmaxf(mb, __shfl_xor_sync(0xffffffffu, mb, 2));
        const float mna = fmaxf(m_a, ma), mnb = fmaxf(m_b, mb);
        const float alfa = fexp2(m_a - mna), alfb = fexp2(m_b - mnb);
        m_a = mna; m_b = mnb;

        // exp + P hi/lo fragments in registers (no smem round-trip)
        uint32_t ph[8][2], pl[8][2];
        float pa = 0.0f, pb = 0.0f;
        #pragma unroll
        for (int j = 0; j < 8; j++) {
            float p0 = fexp2(s[j][0] - mna);
            float p1 = fexp2(s[j][1] - mna);
            float p2 = fexp2(s[j][2] - mnb);
            float p3 = fexp2(s[j][3] - mnb);
            pa += p0 + p1;
            pb += p2 + p3;
            __nv_bfloat162 h0 = __float22bfloat162_rn(make_float2(p0, p1));
            __nv_bfloat162 h1 = __float22bfloat162_rn(make_float2(p2, p3));
            ph[j][0] = *(uint32_t*)&h0;
            ph[j][1] = *(uint32_t*)&h1;
            __nv_bfloat162 l0 = __float22bfloat162_rn(make_float2(
                p0 - __bfloat162float(h0.x), p1 - __bfloat162float(h0.y)));
            __nv_bfloat162 l1 = __float22bfloat162_rn(make_float2(
                p2 - __bfloat162float(h1.x), p3 - __bfloat162float(h1.y)));
            pl[j][0] = *(uint32_t*)&l0;
            pl[j][1] = *(uint32_t*)&l1;
        }
        pa += __shfl_xor_sync(0xffffffffu, pa, 1);
        pa += __shfl_xor_sync(0xffffffffu, pa, 2);
        pb += __shfl_xor_sync(0xffffffffu, pb, 1);
        pb += __shfl_xor_sync(0xffffffffu, pb, 2);
        l_a = l_a * alfa + pa;
        l_b = l_b * alfb + pb;
        #pragma unroll
        for (int j = 0; j < 8; j++) {
            o[j][0] *= alfa; o[j][1] *= alfa;
            o[j][2] *= alfb; o[j][3] *= alfb;
        }

        // ---- partial O += P V over own t-half (16 rows x all 64 d), 3 passes ----
        #pragma unroll
        for (int jd = 0; jd < 8; jd++) {
            uint32_t vh[8], vl[8];
            uint32_t vb = (uint32_t)((8 * jd + brow) * 272 + bko * 2 + h * 128);
            LDSM4(vh[0], vh[1], vh[2], vh[3], sm + VHI_O + vb);
            LDSM4(vh[4], vh[5], vh[6], vh[7], sm + VHI_O + vb + 64);
            LDSM4(vl[0], vl[1], vl[2], vl[3], sm + VLO_O + vb);
            LDSM4(vl[4], vl[5], vl[6], vl[7], sm + VLO_O + vb + 64);
            float* d = o[jd];
            #pragma unroll
            for (int kt = 0; kt < 4; kt++) {
                uint32_t a[4]  = {ph[2 * kt][0], ph[2 * kt][1], ph[2 * kt + 1][0], ph[2 * kt + 1][1]};
                uint32_t al[4] = {pl[2 * kt][0], pl[2 * kt][1], pl[2 * kt + 1][0], pl[2 * kt + 1][1]};
                MMA16816(d, a, vh[2 * kt], vh[2 * kt + 1]);
                MMA16816(d, a, vl[2 * kt], vl[2 * kt + 1]);
                MMA16816(d, al, vh[2 * kt], vh[2 * kt + 1]);
            }
        }
    }

    // ---- epilogue: merge the two half-softmax partials ----
    __syncthreads();  // all compute done before reusing K/BS regions
    float* Xo = (float*)(smem + XO_O);
    float* Mx = (float*)(smem + MX_O);
    float* Lx = (float*)(smem + LX_O);
    if (h == 1) {
        #pragma unroll
        for (int jd = 0; jd < 8; jd++) {
            int cc = 8 * jd + 2 * tg;
            *(float2*)&Xo[ua * 68 + cc] = make_float2(o[jd][0], o[jd][1]);
            *(float2*)&Xo[ub * 68 + cc] = make_float2(o[jd][2], o[jd][3]);
        }
        if (tg == 0) { Mx[ua] = m_a; Mx[ub] = m_b; Lx[ua] = l_a; Lx[ub] = l_b; }
    }
    PAIR_BAR(bar_id);
    if (h == 0) {
        const float m1a = Mx[ua], m1b = Mx[ub];
        const float l1a = Lx[ua], l1b = Lx[ub];
        const float mA = fmaxf(m_a, m1a), mB = fmaxf(m_b, m1b);
        const float a0A = fexp2(m_a - mA), a1A = fexp2(m1a - mA);
        const float a0B = fexp2(m_b - mB), a1B = fexp2(m1b - mB);
        const float invA = 1.0f / (l_a * a0A + l1a * a1A);
        const float invB = 1.0f / (l_b * a0B + l1b * a1B);
        float* orow_a = out + ((size_t)b * SEQ + u0 + ua) * DKE;
        float* orow_b = out + ((size_t)b * SEQ + u0 + ub) * DKE;
        #pragma unroll
        for (int jd = 0; jd < 8; jd++) {
            int cc = 8 * jd + 2 * tg;
            float2 xa = *(float2*)&Xo[ua * 68 + cc];
            float2 xb = *(float2*)&Xo[ub * 68 + cc];
            float2 ra, rb;
            ra.x = (o[jd][0] * a0A + xa.x * a1A) * invA;
            ra.y = (o[jd][1] * a0A + xa.y * a1A) * invA;
            rb.x = (o[jd][2] * a0B + xb.x * a1B) * invB;
            rb.y = (o[jd][3] * a0B + xb.y * a1B) * invB;
            *(float2*)(orow_a + cc) = ra;
            *(float2*)(orow_b + cc) = rb;
        }
    }
}

extern "C" void kernel_launch(void* const* d_in, const int* in_sizes, int n_in,
                              void* d_out, int out_size) {
    const float* Q  = (const float*)d_in[0];
    const float* K  = (const float*)d_in[1];
    const float* V  = (const float*)d_in[2];
    const float* Kr = (const float*)d_in[3];
    float* out = (float*)d_out;

    cudaFuncSetAttribute(attn_mma_kernel, cudaFuncAttributeMaxDynamicSharedMemorySize, SMEM_TOTAL);

    prologue_kernel<<<3208, 256>>>(Q, K, V, Kr);
    attn_mma_kernel<<<dim3(16, BSZ), 512, SMEM_TOTAL>>>(out);
}

// round 12
// speedup vs baseline: 1.1094x; 1.0616x over previous
#include <cuda_runtime.h>
#include <cuda_bf16.h>
#include <cstdint>

#define BSZ 16
#define SEQ 2048
#define DKE 64
#define KR_ROWS 2176

// -------- device-global bf16 split scratch --------
__device__ __align__(16) __nv_bfloat16 g_qhi[BSZ * SEQ * DKE];
__device__ __align__(16) __nv_bfloat16 g_qlo[BSZ * SEQ * DKE];
__device__ __align__(16) __nv_bfloat16 g_khi[BSZ * SEQ * DKE];
__device__ __align__(16) __nv_bfloat16 g_klo[BSZ * SEQ * DKE];
__device__ __align__(16) __nv_bfloat16 g_vthi[BSZ * DKE * SEQ];  // [b][d][t]
__device__ __align__(16) __nv_bfloat16 g_vtlo[BSZ * DKE * SEQ];
__device__ __align__(16) __nv_bfloat16 g_krthi[KR_ROWS * DKE];   // [c][d], c>=SEQ zero

__device__ __forceinline__ uint32_t smem_to_u32(const void* p) {
    uint32_t a;
    asm("{ .reg .u64 t; cvta.to.shared.u64 t, %1; cvt.u32.u64 %0, t; }" : "=r"(a) : "l"(p));
    return a;
}

#define LDSM4(r0, r1, r2, r3, addr) \
    asm volatile("ldmatrix.sync.aligned.m8n8.x4.shared.b16 {%0,%1,%2,%3}, [%4];" \
                 : "=r"(r0), "=r"(r1), "=r"(r2), "=r"(r3) : "r"(addr))

#define MMA16816(d, a, bb0, bb1) \
    asm volatile("mma.sync.aligned.m16n8k16.row.col.f32.bf16.bf16.f32 " \
                 "{%0,%1,%2,%3},{%4,%5,%6,%7},{%8,%9},{%0,%1,%2,%3};" \
                 : "+f"((d)[0]), "+f"((d)[1]), "+f"((d)[2]), "+f"((d)[3]) \
                 : "r"((a)[0]), "r"((a)[1]), "r"((a)[2]), "r"((a)[3]), "r"(bb0), "r"(bb1))

#define CP16(dst, src) \
    asm volatile("cp.async.cg.shared.global [%0], [%1], 16;" :: "r"(dst), "l"(src))
#define CP_COMMIT() asm volatile("cp.async.commit_group;")
#define CP_WAIT0()  asm volatile("cp.async.wait_group 0;")
#define PAIR_BAR(id) asm volatile("bar.sync %0, 64;" :: "r"(id) : "memory")

#define C_SCALE 0.1803368801111204f  /* log2(e)/sqrt(64) */

__device__ __forceinline__ float fexp2(float x) {
    x = fmaxf(x, -126.0f);
    float n = rintf(x), f = x - n;
    float r = 0.00133335581464f;
    r = fmaf(r, f, 0.00961812910763f);
    r = fmaf(r, f, 0.0555041086648f);
    r = fmaf(r, f, 0.2402265069591f);
    r = fmaf(r, f, 0.69314718056f);
    r = fmaf(r, f, 1.0f);
    return r * __int_as_float(((int)n + 127) << 23);
}

// -------- merged prologue: 3208 blocks x 256 threads --------
__global__ void prologue_kernel(const float* __restrict__ Q, const float* __restrict__ K,
                                const float* __restrict__ V, const float* __restrict__ Kr) {
    __shared__ float tile[32][33];
    const int bx = blockIdx.x, tid = threadIdx.x;
    if (bx < 1024) {
        const bool isQ = bx < 512;
        const float* src = isQ ? Q : K;
        __nv_bfloat16* hi = isQ ? g_qhi : g_khi;
        __nv_bfloat16* lo = isQ ? g_qlo : g_klo;
        const int base = (bx & 511) * 4096 + tid * 4;
        #pragma unroll
        for (int k = 0; k < 4; k++) {
            int i = base + k * 1024;
            float4 x = *(const float4*)(src + i);
            __nv_bfloat162 h0 = __float22bfloat162_rn(make_float2(x.x, x.y));
            __nv_bfloat162 h1 = __float22bfloat162_rn(make_float2(x.z, x.w));
            *(__nv_bfloat162*)(hi + i) = h0;
            *(__nv_bfloat162*)(hi + i + 2) = h1;
            __nv_bfloat162 l0 = __float22bfloat162_rn(make_float2(
                x.x - __bfloat162float(h0.x), x.y - __bfloat162float(h0.y)));
            __nv_bfloat162 l1 = __float22bfloat162_rn(make_float2(
                x.z - __bfloat162float(h1.x), x.w - __bfloat162float(h1.y)));
            *(__nv_bfloat162*)(lo + i) = l0;
            *(__nv_bfloat162*)(lo + i + 2) = l1;
        }
    } else if (bx < 3072) {
        const int v = bx - 1024;
        const int b = v >> 7, s0 = (v & 63) * 32, d0 = ((v >> 6) & 1) * 32;
        const int tx = tid & 31, ty = tid >> 5;
        const float* ip = V + (size_t)b * SEQ * DKE;
        for (int i = ty; i < 32; i += 8) tile[i][tx] = ip[(size_t)(s0 + i) * DKE + d0 + tx];
        __syncthreads();
        for (int i = ty; i < 32; i += 8) {
            float x = tile[tx][i];
            __nv_bfloat16 h = __float2bfloat16(x);
            size_t oi = ((size_t)b * DKE + d0 + i) * SEQ + s0 + tx;
            g_vthi[oi] = h;
            g_vtlo[oi] = __float2bfloat16(x - __bfloat162float(h));
        }
    } else {
        const int r = bx - 3072;
        const int c0 = (r % 68) * 32, d0 = (r / 68) * 32;
        const int tx = tid & 31, ty = tid >> 5;
        for (int i = ty; i < 32; i += 8) {
            int c = c0 + tx;
            tile[i][tx] = (c < SEQ) ? Kr[(size_t)(d0 + i) * SEQ + c] : 0.0f;
        }
        __syncthreads();
        for (int i = ty; i < 32; i += 8)
            g_krthi[(size_t)(c0 + i) * DKE + d0 + tx] = __float2bfloat16(tile[tx][i]);
    }
}

// -------- smem layout (bytes) --------
#define QHI_O 0            /* 128 rows x 144B, persists whole kernel */
#define QLO_O 18432
#define KHI_O 36864        /* 128 rows x 144B */
#define KLO_O 55296
#define KR_O  73728        /* 256-row ring x 144B */
#define VHI_O 110592       /* 64 rows x 272B */
#define VLO_O 128000
#define BS_O  145408       /* bf16 128 x 136 (272B stride) */
#define SMEM_TOTAL 180224
/* epilogue reuse (dead regions): */
#define XO_O  36864        /* f32 128 rows x 272B (over K tiles) */
#define MX_O  145408       /* f32[128] (over BS) */
#define LX_O  146432       /* f32[128] */

__global__ __launch_bounds__(512, 1)
void attn_mma_kernel(float* __restrict__ out) {
    extern __shared__ char smem[];
    const uint32_t sm = smem_to_u32(smem);
    const int tid = threadIdx.x, w = tid >> 5, l = tid & 31;
    const int g = l >> 2, tg = l & 3;
    const int ws = w & 7;          // row strip
    const int h = w >> 3;          // t-half this warp owns
    const int Rb = ws * 16;
    const int ua = Rb + g, ub = Rb + g + 8;
    const int bar_id = 1 + ws;     // named pair barrier (warps ws, ws+8)
    const int b = blockIdx.y;
    const int u0 = (15 - (int)blockIdx.x) * 128;  // big tiles first
    const int c0 = 1920 - u0;      // Kr window base for it=0

    // ---- kernel prologue staging: Q hi/lo + first KR half ----
    for (int i = tid; i < 1024; i += 512) {
        int r = i >> 3, c = i & 7;
        CP16(sm + QHI_O + r * 144 + c * 16,
             (const char*)(g_qhi + ((size_t)b * SEQ + u0 + r) * DKE + c * 8));
        CP16(sm + QLO_O + r * 144 + c * 16,
             (const char*)(g_qlo + ((size_t)b * SEQ + u0 + r) * DKE + c * 8));
    }
    for (int i = tid; i < 1024; i += 512) {
        int r = i >> 3, c = i & 7;
        CP16(sm + KR_O + r * 144 + c * 16,
             (const char*)(g_krthi + (size_t)(c0 + r) * DKE + c * 8));
    }
    CP_COMMIT();
    CP_WAIT0();
    __syncthreads();

    const int brow = l & 7;
    const int bko = (l >> 3) * 8;
    const int qrow = Rb + (l & 15);
    const int qko = ((l >> 4) & 1) * 8;

    float m_a = -1e30f, m_b = -1e30f, l_a = 0.0f, l_b = 0.0f;
    float o[8][4];
    #pragma unroll
    for (int j = 0; j < 8; j++) { o[j][0] = o[j][1] = o[j][2] = o[j][3] = 0.0f; }

    const int nIter = u0 / 128 + 1;
    for (int it = 0; it < nIter; ++it) {
        const int t0 = it * 128;
        __syncthreads();  // previous K/V tiles + dead KR half fully consumed

        // ---- stage K(it), V(it), and this window's new KR half ----
        for (int i = tid; i < 1024; i += 512) {
            int r = i >> 3, c = i & 7;
            CP16(sm + KHI_O + r * 144 + c * 16,
                 (const char*)(g_khi + ((size_t)b * SEQ + t0 + r) * DKE + c * 8));
            CP16(sm + KLO_O + r * 144 + c * 16,
                 (const char*)(g_klo + ((size_t)b * SEQ + t0 + r) * DKE + c * 8));
        }
        {
            const int physbase = 128 * ((it + 1) & 1);     // ring slot for new half
            const int gbase = c0 + 128 * (it + 1);
            for (int i = tid; i < 1024; i += 512) {
                int r = i >> 3, c = i & 7;
                CP16(sm + KR_O + (physbase + r) * 144 + c * 16,
                     (const char*)(g_krthi + (size_t)(gbase + r) * DKE + c * 8));
            }
        }
        for (int i = tid; i < 1024; i += 512) {
            int d = i >> 4, c = i & 15;
            size_t src = ((size_t)b * DKE + d) * SEQ + t0 + c * 8;
            CP16(sm + VHI_O + d * 272 + c * 16, (const char*)(g_vthi + src));
            CP16(sm + VLO_O + d * 272 + c * 16, (const char*)(g_vtlo + src));
        }
        CP_COMMIT();
        CP_WAIT0();
        __syncthreads();

        // ---- Q fragments (reloaded per iter from persistent smem Q) ----
        uint32_t qh[4][4], ql[4][4];
        #pragma unroll
        for (int c = 0; c < 4; c++) {
            uint32_t off = (uint32_t)(qrow * 144 + (c * 16 + qko) * 2);
            LDSM4(qh[c][0], qh[c][1], qh[c][2], qh[c][3], sm + QHI_O + off);
            LDSM4(ql[c][0], ql[c][1], ql[c][2], ql[c][3], sm + QLO_O + off);
        }

        // ---- S = Q K^T, 3 passes, 2-way interleaved j-pairs ----
        float s[8][4];
        #pragma unroll
        for (int j = 0; j < 8; j++) s[j][0] = s[j][1] = s[j][2] = s[j][3] = 0.0f;
        #pragma unroll
        for (int jp = 0; jp < 4; jp++) {
            const int j0 = 2 * jp, j1 = 2 * jp + 1;
            const uint32_t ab0 = (uint32_t)((8 * (8 * h + j0) + brow) * 144 + bko * 2);
            const uint32_t ab1 = (uint32_t)((8 * (8 * h + j1) + brow) * 144 + bko * 2);
            uint32_t b0[8], b1[8];
            // hi B-tiles: qh*bh and ql*bh passes, interleaved across the pair
            LDSM4(b0[0], b0[1], b0[2], b0[3], sm + KHI_O + ab0);
            LDSM4(b0[4], b0[5], b0[6], b0[7], sm + KHI_O + ab0 + 64);
            LDSM4(b1[0], b1[1], b1[2], b1[3], sm + KHI_O + ab1);
            LDSM4(b1[4], b1[5], b1[6], b1[7], sm + KHI_O + ab1 + 64);
            #pragma unroll
            for (int c = 0; c < 4; c++) {
                MMA16816(s[j0], qh[c], b0[2 * c], b0[2 * c + 1]);
                MMA16816(s[j1], qh[c], b1[2 * c], b1[2 * c + 1]);
                MMA16816(s[j0], ql[c], b0[2 * c], b0[2 * c + 1]);
                MMA16816(s[j1], ql[c], b1[2 * c], b1[2 * c + 1]);
            }
            // lo B-tiles: qh*bl pass
            LDSM4(b0[0], b0[1], b0[2], b0[3], sm + KLO_O + ab0);
            LDSM4(b0[4], b0[5], b0[6], b0[7], sm + KLO_O + ab0 + 64);
            LDSM4(b1[0], b1[1], b1[2], b1[3], sm + KLO_O + ab1);
            LDSM4(b1[4], b1[5], b1[6], b1[7], sm + KLO_O + ab1 + 64);
            #pragma unroll
            for (int c = 0; c < 4; c++) {
                MMA16816(s[j0], qh[c], b0[2 * c], b0[2 * c + 1]);
                MMA16816(s[j1], qh[c], b1[2 * c], b1[2 * c + 1]);
            }
        }

        // ---- bias GEMM (Qhi only): 9 window tiles as 4 pairs + 1, ring-indexed ----
        {
            __nv_bfloat16* Bs = (__nv_bfloat16*)(smem + BS_O);
            const int jb0 = 14 - 2 * ws + 9 * h;
            #pragma unroll
            for (int pp = 0; pp < 4; pp++) {
                const int ja = jb0 + 2 * pp, jc = ja + 1;
                const int jpa = (ja + 16 * it) & 31, jpc = (jc + 16 * it) & 31;
                uint32_t ka[8], kc[8];
                const uint32_t aa = (uint32_t)((8 * jpa + brow) * 144 + bko * 2);
                const uint32_t ac = (uint32_t)((8 * jpc + brow) * 144 + bko * 2);
                LDSM4(ka[0], ka[1], ka[2], ka[3], sm + KR_O + aa);
                LDSM4(ka[4], ka[5], ka[6], ka[7], sm + KR_O + aa + 64);
                LDSM4(kc[0], kc[1], kc[2], kc[3], sm + KR_O + ac);
                LDSM4(kc[4], kc[5], kc[6], kc[7], sm + KR_O + ac + 64);
                float da[4] = {0, 0, 0, 0}, dc[4] = {0, 0, 0, 0};
                #pragma unroll
                for (int c = 0; c < 4; c++) {
                    MMA16816(da, qh[c], ka[2 * c], ka[2 * c + 1]);
                    MMA16816(dc, qh[c], kc[2 * c], kc[2 * c + 1]);
                }
                int cca = 8 * ja + 2 * tg, ccc = 8 * jc + 2 * tg;
                int ta = cca + ua - 127, tb = cca + ub - 127;
                if ((unsigned)ta < 128u)       Bs[ua * 136 + ta] = __float2bfloat16(da[0]);
                if ((unsigned)(ta + 1) < 128u) Bs[ua * 136 + ta + 1] = __float2bfloat16(da[1]);
                if ((unsigned)tb < 128u)       Bs[ub * 136 + tb] = __float2bfloat16(da[2]);
                if ((unsigned)(tb + 1) < 128u) Bs[ub * 136 + tb + 1] = __float2bfloat16(da[3]);
                ta = ccc + ua - 127; tb = ccc + ub - 127;
                if ((unsigned)ta < 128u)       Bs[ua * 136 + ta] = __float2bfloat16(dc[0]);
                if ((unsigned)(ta + 1) < 128u) Bs[ua * 136 + ta + 1] = __float2bfloat16(dc[1]);
                if ((unsigned)tb < 128u)       Bs[ub * 136 + tb] = __float2bfloat16(dc[2]);
                if ((unsigned)(tb + 1) < 128u) Bs[ub * 136 + tb + 1] = __float2bfloat16(dc[3]);
            }
            {   // 9th tile
                const int j = jb0 + 8;
                const int jp = (j + 16 * it) & 31;
                uint32_t kb[8];
                const uint32_t ab = (uint32_t)((8 * jp + brow) * 144 + bko * 2);
                LDSM4(kb[0], kb[1], kb[2], kb[3], sm + KR_O + ab);
                LDSM4(kb[4], kb[5], kb[6], kb[7], sm + KR_O + ab + 64);
                float d[4] = {0, 0, 0, 0};
                #pragma unroll
                for (int c = 0; c < 4; c++)
                    MMA16816(d, qh[c], kb[2 * c], kb[2 * c + 1]);
                int cc = 8 * j + 2 * tg;
                int ta = cc + ua - 127, tb = cc + ub - 127;
                if ((unsigned)ta < 128u)       Bs[ua * 136 + ta] = __float2bfloat16(d[0]);
                if ((unsigned)(ta + 1) < 128u) Bs[ua * 136 + ta + 1] = __float2bfloat16(d[1]);
                if ((unsigned)tb < 128u)       Bs[ub * 136 + tb] = __float2bfloat16(d[2]);
                if ((unsigned)(tb + 1) < 128u) Bs[ub * 136 + tb + 1] = __float2bfloat16(d[3]);
            }
        }
        PAIR_BAR(bar_id);  // both halves' bias scatter visible to the pair

        // ---- logits + causal mask (own half) ----
        {
            const __nv_bfloat16* Bs = (const __nv_bfloat16*)(smem + BS_O);
            #pragma unroll
            for (int j = 0; j < 8; j++) {
                int cc = 64 * h + 8 * j + 2 * tg;
                __nv_bfloat162 ba = *(__nv_bfloat162*)&Bs[ua * 136 + cc];
                __nv_bfloat162 bb = *(__nv_bfloat162*)&Bs[ub * 136 + cc];
                s[j][0] = (s[j][0] + __bfloat162float(ba.x)) * C_SCALE;
                s[j][1] = (s[j][1] + __bfloat162float(ba.y)) * C_SCALE;
                s[j][2] = (s[j][2] + __bfloat162float(bb.x)) * C_SCALE;
                s[j][3] = (s[j][3] + __bfloat162float(bb.y)) * C_SCALE;
            }
        }
        if (t0 == u0) {
            #pragma unroll
            for (int j = 0; j < 8; j++) {
                int cc = 64 * h + 8 * j + 2 * tg;
                if (cc > ua)     s[j][0] = -1e30f;
                if (cc + 1 > ua) s[j][1] = -1e30f;
                if (cc > ub)     s[j][2] = -1e30f;
                if (cc + 1 > ub) s[j][3] = -1e30f;
            }
        }

        // ---- warp-local online softmax over own half ----
        float ma = -1e30f, mb = -1e30f;
        #pragma unroll
        for (int j = 0; j < 8; j++) {
            ma = fmaxf(ma, fmaxf(s[j][0], s[j][1]));
            mb = fmaxf(mb, fmaxf(s[j][2], s[j][3]));
        }
        ma = fmaxf(ma, __shfl_xor_sync(0xffffffffu, ma, 1));
        ma = fmaxf(ma, __shfl_xor_sync(0xffffffffu, ma, 2));
        mb = fmaxf(mb, __shfl_xor_sync(0xffffffffu, mb, 1));
        mb = fmaxf(mb, __shfl_xor_sync(0xffffffffu, mb, 2));
        const float mna = fmaxf(m_a, ma), mnb = fmaxf(m_b, mb);
        const float alfa = fexp2(m_a - mna), alfb = fexp2(m_b - mnb);
        m_a = mna; m_b = mnb;

        // exp + P hi/lo fragments in registers
        uint32_t ph[8][2], pl[8][2];
        float pa = 0.0f, pb = 0.0f;
        #pragma unroll
        for (int j = 0; j < 8; j++) {
            float p0 = fexp2(s[j][0] - mna);
            float p1 = fexp2(s[j][1] - mna);
            float p2 = fexp2(s[j][2] - mnb);
            float p3 = fexp2(s[j][3] - mnb);
            pa += p0 + p1;
            pb += p2 + p3;
            __nv_bfloat162 h0 = __float22bfloat162_rn(make_float2(p0, p1));
            __nv_bfloat162 h1 = __float22bfloat162_rn(make_float2(p2, p3));
            ph[j][0] = *(uint32_t*)&h0;
            ph[j][1] = *(uint32_t*)&h1;
            __nv_bfloat162 l0 = __float22bfloat162_rn(make_float2(
                p0 - __bfloat162float(h0.x), p1 - __bfloat162float(h0.y)));
            __nv_bfloat162 l1 = __float22bfloat162_rn(make_float2(
                p2 - __bfloat162float(h1.x), p3 - __bfloat162float(h1.y)));
            pl[j][0] = *(uint32_t*)&l0;
            pl[j][1] = *(uint32_t*)&l1;
        }
        pa += __shfl_xor_sync(0xffffffffu, pa, 1);
        pa += __shfl_xor_sync(0xffffffffu, pa, 2);
        pb += __shfl_xor_sync(0xffffffffu, pb, 1);
        pb += __shfl_xor_sync(0xffffffffu, pb, 2);
        l_a = l_a * alfa + pa;
        l_b = l_b * alfb + pb;
        #pragma unroll
        for (int j = 0; j < 8; j++) {
            o[j][0] *= alfa; o[j][1] *= alfa;
            o[j][2] *= alfb; o[j][3] *= alfb;
        }

        // ---- partial O += P V over own t-half, 3 passes, 2-way jd-pairs ----
        #pragma unroll
        for (int jq = 0; jq < 4; jq++) {
            const int jd0 = 2 * jq, jd1 = 2 * jq + 1;
            const uint32_t vb0 = (uint32_t)((8 * jd0 + brow) * 272 + bko * 2 + h * 128);
            const uint32_t vb1 = (uint32_t)((8 * jd1 + brow) * 272 + bko * 2 + h * 128);
            uint32_t v0[8], v1[8];
            // hi V-tiles: a*vh and al*vh passes
            LDSM4(v0[0], v0[1], v0[2], v0[3], sm + VHI_O + vb0);
            LDSM4(v0[4], v0[5], v0[6], v0[7], sm + VHI_O + vb0 + 64);
            LDSM4(v1[0], v1[1], v1[2], v1[3], sm + VHI_O + vb1);
            LDSM4(v1[4], v1[5], v1[6], v1[7], sm + VHI_O + vb1 + 64);
            #pragma unroll
            for (int kt = 0; kt < 4; kt++) {
                uint32_t a[4]  = {ph[2 * kt][0], ph[2 * kt][1], ph[2 * kt + 1][0], ph[2 * kt + 1][1]};
                uint32_t al[4] = {pl[2 * kt][0], pl[2 * kt][1], pl[2 * kt + 1][0], pl[2 * kt + 1][1]};
                MMA16816(o[jd0], a, v0[2 * kt], v0[2 * kt + 1]);
                MMA16816(o[jd1], a, v1[2 * kt], v1[2 * kt + 1]);
                MMA16816(o[jd0], al, v0[2 * kt], v0[2 * kt + 1]);
                MMA16816(o[jd1], al, v1[2 * kt], v1[2 * kt + 1]);
            }
            // lo V-tiles: a*vl pass
            LDSM4(v0[0], v0[1], v0[2], v0[3], sm + VLO_O + vb0);
            LDSM4(v0[4], v0[5], v0[6], v0[7], sm + VLO_O + vb0 + 64);
            LDSM4(v1[0], v1[1], v1[2], v1[3], sm + VLO_O + vb1);
            LDSM4(v1[4], v1[5], v1[6], v1[7], sm + VLO_O + vb1 + 64);
            #pragma unroll
            for (int kt = 0; kt < 4; kt++) {
                uint32_t a[4] = {ph[2 * kt][0], ph[2 * kt][1], ph[2 * kt + 1][0], ph[2 * kt + 1][1]};
                MMA16816(o[jd0], a, v0[2 * kt], v0[2 * kt + 1]);
                MMA16816(o[jd1], a, v1[2 * kt], v1[2 * kt + 1]);
            }
        }
    }

    // ---- epilogue: merge the two half-softmax partials ----
    __syncthreads();  // all compute done before reusing K/BS regions
    float* Xo = (float*)(smem + XO_O);
    float* Mx = (float*)(smem + MX_O);
    float* Lx = (float*)(smem + LX_O);
    if (h == 1) {
        #pragma unroll
        for (int jd = 0; jd < 8; jd++) {
            int cc = 8 * jd + 2 * tg;
            *(float2*)&Xo[ua * 68 + cc] = make_float2(o[jd][0], o[jd][1]);
            *(float2*)&Xo[ub * 68 + cc] = make_float2(o[jd][2], o[jd][3]);
        }
        if (tg == 0) { Mx[ua] = m_a; Mx[ub] = m_b; Lx[ua] = l_a; Lx[ub] = l_b; }
    }
    PAIR_BAR(bar_id);
    if (h == 0) {
        const float m1a = Mx[ua], m1b = Mx[ub];
        const float l1a = Lx[ua], l1b = Lx[ub];
        const float mA = fmaxf(m_a, m1a), mB = fmaxf(m_b, m1b);
        const float a0A = fexp2(m_a - mA), a1A = fexp2(m1a - mA);
        const float a0B = fexp2(m_b - mB), a1B = fexp2(m1b - mB);
        const float invA = 1.0f / (l_a * a0A + l1a * a1A);
        const float invB = 1.0f / (l_b * a0B + l1b * a1B);
        float* orow_a = out + ((size_t)b * SEQ + u0 + ua) * DKE;
        float* orow_b = out + ((size_t)b * SEQ + u0 + ub) * DKE;
        #pragma unroll
        for (int jd = 0; jd < 8; jd++) {
            int cc = 8 * jd + 2 * tg;
            float2 xa = *(float2*)&Xo[ua * 68 + cc];
            float2 xb = *(float2*)&Xo[ub * 68 + cc];
            float2 ra, rb;
            ra.x = (o[jd][0] * a0A + xa.x * a1A) * invA;
            ra.y = (o[jd][1] * a0A + xa.y * a1A) * invA;
            rb.x = (o[jd][2] * a0B + xb.x * a1B) * invB;
            rb.y = (o[jd][3] * a0B + xb.y * a1B) * invB;
            *(float2*)(orow_a + cc) = ra;
            *(float2*)(orow_b + cc) = rb;
        }
    }
}

extern "C" void kernel_launch(void* const* d_in, const int* in_sizes, int n_in,
                              void* d_out, int out_size) {
    const float* Q  = (const float*)d_in[0];
    const float* K  = (const float*)d_in[1];
    const float* V  = (const float*)d_in[2];
    const float* Kr = (const float*)d_in[3];
    float* out = (float*)d_out;

    cudaFuncSetAttribute(attn_mma_kernel, cudaFuncAttributeMaxDynamicSharedMemorySize, SMEM_TOTAL);

    prologue_kernel<<<3208, 256>>>(Q, K, V, Kr);
    attn_mma_kernel<<<dim3(16, BSZ), 512, SMEM_TOTAL>>>(out);
}

// round 14
// speedup vs baseline: 1.1922x; 1.0746x over previous
#include <cuda_runtime.h>
#include <cuda_bf16.h>
#include <cstdint>

#define BSZ 16
#define SEQ 2048
#define DKE 64
#define KR_ROWS 2176
#define C_SCALE 0.1803368801111204f  /* log2(e)/sqrt(64) */

// -------- device-global scratch --------
__device__ __align__(16) float         g_qt[BSZ * SEQ * DKE];   // tf32-rounded, pre-scaled
__device__ __align__(16) __nv_bfloat16 g_qb[BSZ * SEQ * DKE];   // bf16, pre-scaled (bias GEMM)
__device__ __align__(16) float         g_kt[BSZ * SEQ * DKE];   // tf32-rounded
__device__ __align__(16) float         g_vtf[BSZ * DKE * SEQ];  // [b][d][t], tf32-rounded
__device__ __align__(16) __nv_bfloat16 g_krt[KR_ROWS * DKE];    // [c][d], c>=SEQ zero

__device__ __forceinline__ uint32_t smem_to_u32(const void* p) {
    uint32_t a;
    asm("{ .reg .u64 t; cvta.to.shared.u64 t, %1; cvt.u32.u64 %0, t; }" : "=r"(a) : "l"(p));
    return a;
}
__device__ __forceinline__ float tf32r(float x) {
    asm("cvt.rna.tf32.f32 %0, %0;" : "+f"(x));
    return x;
}
__device__ __forceinline__ float ex2(float x) {
    float y;
    asm("ex2.approx.f32 %0, %1;" : "=f"(y) : "f"(x));
    return y;
}

#define LDSM4(r0, r1, r2, r3, addr) \
    asm volatile("ldmatrix.sync.aligned.m8n8.x4.shared.b16 {%0,%1,%2,%3}, [%4];" \
                 : "=r"(r0), "=r"(r1), "=r"(r2), "=r"(r3) : "r"(addr))

#define MMA16816(d, a, bb0, bb1) \
    asm volatile("mma.sync.aligned.m16n8k16.row.col.f32.bf16.bf16.f32 " \
                 "{%0,%1,%2,%3},{%4,%5,%6,%7},{%8,%9},{%0,%1,%2,%3};" \
                 : "+f"((d)[0]), "+f"((d)[1]), "+f"((d)[2]), "+f"((d)[3]) \
                 : "r"((a)[0]), "r"((a)[1]), "r"((a)[2]), "r"((a)[3]), "r"(bb0), "r"(bb1))

#define MMAT32(d, a, bb0, bb1) \
    asm volatile("mma.sync.aligned.m16n8k8.row.col.f32.tf32.tf32.f32 " \
                 "{%0,%1,%2,%3},{%4,%5,%6,%7},{%8,%9},{%0,%1,%2,%3};" \
                 : "+f"((d)[0]), "+f"((d)[1]), "+f"((d)[2]), "+f"((d)[3]) \
                 : "r"((a)[0]), "r"((a)[1]), "r"((a)[2]), "r"((a)[3]), "r"(bb0), "r"(bb1))

#define CP16(dst, src) \
    asm volatile("cp.async.cg.shared.global [%0], [%1], 16;" :: "r"(dst), "l"(src))
#define CP_COMMIT() asm volatile("cp.async.commit_group;")
#define CP_WAIT0()  asm volatile("cp.async.wait_group 0;")
#define PAIR_BAR(id) asm volatile("bar.sync %0, 64;" :: "r"(id) : "memory")

// -------- merged prologue: 3208 blocks x 256 threads --------
__global__ void prologue_kernel(const float* __restrict__ Q, const float* __restrict__ K,
                                const float* __restrict__ V, const float* __restrict__ Kr) {
    __shared__ float tile[32][33];
    const int bx = blockIdx.x, tid = threadIdx.x;
    if (bx < 512) {  // Q: scale, tf32-round, + bf16 copy
        const int base = bx * 4096 + tid * 4;
        #pragma unroll
        for (int k = 0; k < 4; k++) {
            int i = base + k * 1024;
            float4 x = *(const float4*)(Q + i);
            x.x *= C_SCALE; x.y *= C_SCALE; x.z *= C_SCALE; x.w *= C_SCALE;
            float4 r;
            r.x = tf32r(x.x); r.y = tf32r(x.y); r.z = tf32r(x.z); r.w = tf32r(x.w);
            *(float4*)(g_qt + i) = r;
            __nv_bfloat162 h0 = __float22bfloat162_rn(make_float2(x.x, x.y));
            __nv_bfloat162 h1 = __float22bfloat162_rn(make_float2(x.z, x.w));
            *(__nv_bfloat162*)(g_qb + i) = h0;
            *(__nv_bfloat162*)(g_qb + i + 2) = h1;
        }
    } else if (bx < 1024) {  // K: tf32-round
        const int base = (bx - 512) * 4096 + tid * 4;
        #pragma unroll
        for (int k = 0; k < 4; k++) {
            int i = base + k * 1024;
            float4 x = *(const float4*)(K + i);
            float4 r;
            r.x = tf32r(x.x); r.y = tf32r(x.y); r.z = tf32r(x.z); r.w = tf32r(x.w);
            *(float4*)(g_kt + i) = r;
        }
    } else if (bx < 3072) {  // V: transpose + tf32-round
        const int v = bx - 1024;
        const int b = v >> 7, s0 = (v & 63) * 32, d0 = ((v >> 6) & 1) * 32;
        const int tx = tid & 31, ty = tid >> 5;
        const float* ip = V + (size_t)b * SEQ * DKE;
        for (int i = ty; i < 32; i += 8) tile[i][tx] = ip[(size_t)(s0 + i) * DKE + d0 + tx];
        __syncthreads();
        for (int i = ty; i < 32; i += 8)
            g_vtf[((size_t)b * DKE + d0 + i) * SEQ + s0 + tx] = tf32r(tile[tx][i]);
    } else {  // Kr: transpose, bf16
        const int r = bx - 3072;
        const int c0 = (r % 68) * 32, d0 = (r / 68) * 32;
        const int tx = tid & 31, ty = tid >> 5;
        for (int i = ty; i < 32; i += 8) {
            int c = c0 + tx;
            tile[i][tx] = (c < SEQ) ? Kr[(size_t)(d0 + i) * SEQ + c] : 0.0f;
        }
        __syncthreads();
        for (int i = ty; i < 32; i += 8)
            g_krt[(size_t)(c0 + i) * DKE + d0 + tx] = __float2bfloat16(tile[tx][i]);
    }
}

// -------- smem layout (bytes) --------
#define QT_O 0          /* f32 128 x 272B, persistent */
#define QB_O 34816      /* bf16 128 x 144B, persistent */
#define K_O  53248      /* f32 128 x 272B */
#define KR_O 88064      /* bf16 256 x 144B, restaged fully each iter */
#define V_O  124928     /* f32 64 x 528B */
#define BS_O 158720     /* bf16 128 x 272B stride */
#define P_O  53248      /* f32 128 x 528B, aliases K+KR (dead post-bias) */
#define SMEM_TOTAL 193536
/* epilogue aliases */
#define XO_O 0          /* f32 128 x 68 floats (over QT) */
#define MX_O 34816      /* f32[128] (over QB) */
#define LX_O 35840

__global__ __launch_bounds__(512, 1)
void attn_mma_kernel(float* __restrict__ out) {
    extern __shared__ char smem[];
    const uint32_t sm = smem_to_u32(smem);
    const int tid = threadIdx.x, w = tid >> 5, l = tid & 31;
    const int g = l >> 2, tg = l & 3;
    const int ws = w & 7;          // row strip
    const int h = w >> 3;          // t-half this warp owns
    const int Rb = ws * 16;
    const int ua = Rb + g, ub = Rb + g + 8;
    const int bar_id = 1 + ws;
    const int b = blockIdx.y;
    const int u0 = (15 - (int)blockIdx.x) * 128;  // big tiles first
    const int c0 = 1920 - u0;

    // ---- persistent staging: Q tf32 + Q bf16 ----
    for (int i = tid; i < 2048; i += 512) {
        int r = i >> 4, c = i & 15;
        CP16(sm + QT_O + r * 272 + c * 16,
             (const char*)(g_qt + ((size_t)b * SEQ + u0 + r) * DKE + c * 4));
    }
    for (int i = tid; i < 1024; i += 512) {
        int r = i >> 3, c = i & 7;
        CP16(sm + QB_O + r * 144 + c * 16,
             (const char*)(g_qb + ((size_t)b * SEQ + u0 + r) * DKE + c * 8));
    }
    CP_COMMIT();
    CP_WAIT0();
    __syncthreads();

    // lane-constant ldmatrix bases
    const uint32_t qa_base = sm + QT_O +
        (uint32_t)((Rb + (l & 7) + ((l >> 3) & 1) * 8) * 272 + ((l >> 4) & 1) * 16);
    const uint32_t pa_base = sm + P_O +
        (uint32_t)((Rb + (l & 7) + ((l >> 3) & 1) * 8) * 528 + ((l >> 4) & 1) * 16 + h * 256);
    const uint32_t vb_base = sm + V_O +
        (uint32_t)((l & 7) * 528 + (l >> 3) * 16 + h * 256);
    const int qrow = Rb + (l & 15);
    const int qko16 = ((l >> 4) & 1) * 16;  // bytes
    const int brow = l & 7;
    const int bk16 = (l >> 3) * 16;         // bytes

    float m_a = -1e30f, m_b = -1e30f, l_a = 0.0f, l_b = 0.0f;
    float o[8][4];
    #pragma unroll
    for (int j = 0; j < 8; j++) { o[j][0] = o[j][1] = o[j][2] = o[j][3] = 0.0f; }

    const int nIter = u0 / 128 + 1;
    for (int it = 0; it < nIter; ++it) {
        const int t0 = it * 128;
        const int c_base = c0 + t0;
        __syncthreads();  // previous tiles (incl. P over K/KR) fully consumed

        // ---- stage K(it) f32, KR window bf16 (full 256 rows), V(it) f32 ----
        for (int i = tid; i < 2048; i += 512) {
            int r = i >> 4, c = i & 15;
            CP16(sm + K_O + r * 272 + c * 16,
                 (const char*)(g_kt + ((size_t)b * SEQ + t0 + r) * DKE + c * 4));
        }
        for (int i = tid; i < 2048; i += 512) {
            int r = i >> 3, c = i & 7;
            CP16(sm + KR_O + r * 144 + c * 16,
                 (const char*)(g_krt + (size_t)(c_base + r) * DKE + c * 8));
        }
        for (int i = tid; i < 2048; i += 512) {
            int r = i >> 5, c = i & 31;
            CP16(sm + V_O + r * 528 + c * 16,
                 (const char*)(g_vtf + ((size_t)b * DKE + r) * SEQ + t0 + c * 4));
        }
        CP_COMMIT();
        CP_WAIT0();
        __syncthreads();

        // ---- S = Q K^T, single-pass tf32 (own 16 rows x own 64 t-cols) ----
        float s[8][4];
        #pragma unroll
        for (int j = 0; j < 8; j++) s[j][0] = s[j][1] = s[j][2] = s[j][3] = 0.0f;
        #pragma unroll
        for (int cp = 0; cp < 4; cp++) {
            uint32_t a0[4], a1[4];
            LDSM4(a0[0], a0[1], a0[2], a0[3], qa_base + (2 * cp) * 32);
            LDSM4(a1[0], a1[1], a1[2], a1[3], qa_base + (2 * cp + 1) * 32);
            #pragma unroll
            for (int jp = 0; jp < 4; jp++) {
                const int j0 = 2 * jp, j1 = 2 * jp + 1;
                uint32_t b0[4], b1[4];
                const uint32_t kb0 = sm + K_O +
                    (uint32_t)((64 * h + 8 * j0 + brow) * 272 + (l >> 3) * 16) + cp * 64;
                const uint32_t kb1 = kb0 + 8 * 272;
                LDSM4(b0[0], b0[1], b0[2], b0[3], kb0);
                LDSM4(b1[0], b1[1], b1[2], b1[3], kb1);
                MMAT32(s[j0], a0, b0[0], b0[1]);
                MMAT32(s[j1], a0, b1[0], b1[1]);
                MMAT32(s[j0], a1, b0[2], b0[3]);
                MMAT32(s[j1], a1, b1[2], b1[3]);
            }
        }

        // ---- bias GEMM bf16 (Qb x Kr window): pair's 18 tiles split 9/9 ----
        {
            uint32_t qh[4][4];
            #pragma unroll
            for (int c = 0; c < 4; c++) {
                uint32_t off = (uint32_t)(qrow * 144 + c * 32 + qko16);
                LDSM4(qh[c][0], qh[c][1], qh[c][2], qh[c][3], sm + QB_O + off);
            }
            __nv_bfloat16* Bs = (__nv_bfloat16*)(smem + BS_O);
            const int jb0 = 14 - 2 * ws + 9 * h;
            #pragma unroll
            for (int jj = 0; jj < 9; jj++) {
                const int jb = jb0 + jj;
                uint32_t kb[8];
                const uint32_t ab = sm + KR_O + (uint32_t)((8 * jb + brow) * 144 + bk16);
                LDSM4(kb[0], kb[1], kb[2], kb[3], ab);
                LDSM4(kb[4], kb[5], kb[6], kb[7], ab + 64);
                float d[4] = {0, 0, 0, 0};
                #pragma unroll
                for (int c = 0; c < 4; c++)
                    MMA16816(d, qh[c], kb[2 * c], kb[2 * c + 1]);
                int cc = 8 * jb + 2 * tg;
                int ta = cc + ua - 127, tb = cc + ub - 127;
                if ((unsigned)ta < 128u)       Bs[ua * 136 + ta] = __float2bfloat16(d[0]);
                if ((unsigned)(ta + 1) < 128u) Bs[ua * 136 + ta + 1] = __float2bfloat16(d[1]);
                if ((unsigned)tb < 128u)       Bs[ub * 136 + tb] = __float2bfloat16(d[2]);
                if ((unsigned)(tb + 1) < 128u) Bs[ub * 136 + tb + 1] = __float2bfloat16(d[3]);
            }
        }
        PAIR_BAR(bar_id);  // both halves' bias scatter visible

        // ---- logits (pre-scaled: just add bias) + causal mask ----
        {
            const __nv_bfloat16* Bs = (const __nv_bfloat16*)(smem + BS_O);
            #pragma unroll
            for (int j = 0; j < 8; j++) {
                int cc = 64 * h + 8 * j + 2 * tg;
                __nv_bfloat162 ba = *(__nv_bfloat162*)&Bs[ua * 136 + cc];
                __nv_bfloat162 bb = *(__nv_bfloat162*)&Bs[ub * 136 + cc];
                s[j][0] += __bfloat162float(ba.x);
                s[j][1] += __bfloat162float(ba.y);
                s[j][2] += __bfloat162float(bb.x);
                s[j][3] += __bfloat162float(bb.y);
            }
        }
        if (t0 == u0) {
            #pragma unroll
            for (int j = 0; j < 8; j++) {
                int cc = 64 * h + 8 * j + 2 * tg;
                if (cc > ua)     s[j][0] = -1e30f;
                if (cc + 1 > ua) s[j][1] = -1e30f;
                if (cc > ub)     s[j][2] = -1e30f;
                if (cc + 1 > ub) s[j][3] = -1e30f;
            }
        }

        // ---- warp-local online softmax ----
        float ma = -1e30f, mb = -1e30f;
        #pragma unroll
        for (int j = 0; j < 8; j++) {
            ma = fmaxf(ma, fmaxf(s[j][0], s[j][1]));
            mb = fmaxf(mb, fmaxf(s[j][2], s[j][3]));
        }
        ma = fmaxf(ma, __shfl_xor_sync(0xffffffffu, ma, 1));
        ma = fmaxf(ma, __shfl_xor_sync(0xffffffffu, ma, 2));
        mb = fmaxf(mb, __shfl_xor_sync(0xffffffffu, mb, 1));
        mb = fmaxf(mb, __shfl_xor_sync(0xffffffffu, mb, 2));
        const float mna = fmaxf(m_a, ma), mnb = fmaxf(m_b, mb);
        const float alfa = ex2(m_a - mna), alfb = ex2(m_b - mnb);
        m_a = mna; m_b = mnb;

        // exp; write P (tf32-rounded f32) to smem (own rows/cols only)
        float pa = 0.0f, pb = 0.0f;
        #pragma unroll
        for (int j = 0; j < 8; j++) {
            const int cc = 64 * h + 8 * j + 2 * tg;
            float p0 = ex2(s[j][0] - mna);
            float p1 = ex2(s[j][1] - mna);
            float p2 = ex2(s[j][2] - mnb);
            float p3 = ex2(s[j][3] - mnb);
            pa += p0 + p1;
            pb += p2 + p3;
            uint32_t t0r, t1r, t2r, t3r;
            asm("cvt.rna.tf32.f32 %0, %1;" : "=r"(t0r) : "f"(p0));
            asm("cvt.rna.tf32.f32 %0, %1;" : "=r"(t1r) : "f"(p1));
            asm("cvt.rna.tf32.f32 %0, %1;" : "=r"(t2r) : "f"(p2));
            asm("cvt.rna.tf32.f32 %0, %1;" : "=r"(t3r) : "f"(p3));
            *(uint2*)(smem + P_O + ua * 528 + cc * 4) = make_uint2(t0r, t1r);
            *(uint2*)(smem + P_O + ub * 528 + cc * 4) = make_uint2(t2r, t3r);
        }
        __syncwarp();
        pa += __shfl_xor_sync(0xffffffffu, pa, 1);
        pa += __shfl_xor_sync(0xffffffffu, pa, 2);
        pb += __shfl_xor_sync(0xffffffffu, pb, 1);
        pb += __shfl_xor_sync(0xffffffffu, pb, 2);
        l_a = l_a * alfa + pa;
        l_b = l_b * alfb + pb;
        #pragma unroll
        for (int j = 0; j < 8; j++) {
            o[j][0] *= alfa; o[j][1] *= alfa;
            o[j][2] *= alfb; o[j][3] *= alfb;
        }

        // ---- partial O += P V, single-pass tf32 (own t-half, all 64 d) ----
        #pragma unroll
        for (int cp = 0; cp < 4; cp++) {
            uint32_t a0[4], a1[4];
            LDSM4(a0[0], a0[1], a0[2], a0[3], pa_base + (2 * cp) * 32);
            LDSM4(a1[0], a1[1], a1[2], a1[3], pa_base + (2 * cp + 1) * 32);
            #pragma unroll
            for (int jq = 0; jq < 4; jq++) {
                const int jd0 = 2 * jq, jd1 = 2 * jq + 1;
                uint32_t v0[4], v1[4];
                LDSM4(v0[0], v0[1], v0[2], v0[3], vb_base + jd0 * (8 * 528) + cp * 64);
                LDSM4(v1[0], v1[1], v1[2], v1[3], vb_base + jd1 * (8 * 528) + cp * 64);
                MMAT32(o[jd0], a0, v0[0], v0[1]);
                MMAT32(o[jd1], a0, v1[0], v1[1]);
                MMAT32(o[jd0], a1, v0[2], v0[3]);
                MMAT32(o[jd1], a1, v1[2], v1[3]);
            }
        }
    }

    // ---- epilogue: merge half-softmax partials ----
    __syncthreads();
    float* Xo = (float*)(smem + XO_O);
    float* Mx = (float*)(smem + MX_O);
    float* Lx = (float*)(smem + LX_O);
    if (h == 1) {
        #pragma unroll
        for (int jd = 0; jd < 8; jd++) {
            int cc = 8 * jd + 2 * tg;
            *(float2*)&Xo[ua * 68 + cc] = make_float2(o[jd][0], o[jd][1]);
            *(float2*)&Xo[ub * 68 + cc] = make_float2(o[jd][2], o[jd][3]);
        }
        if (tg == 0) { Mx[ua] = m_a; Mx[ub] = m_b; Lx[ua] = l_a; Lx[ub] = l_b; }
    }
    PAIR_BAR(bar_id);
    if (h == 0) {
        const float m1a = Mx[ua], m1b = Mx[ub];
        const float l1a = Lx[ua], l1b = Lx[ub];
        const float mA = fmaxf(m_a, m1a), mB = fmaxf(m_b, m1b);
        const float a0A = ex2(m_a - mA), a1A = ex2(m1a - mA);
        const float a0B = ex2(m_b - mB), a1B = ex2(m1b - mB);
        const float invA = 1.0f / (l_a * a0A + l1a * a1A);
        const float invB = 1.0f / (l_b * a0B + l1b * a1B);
        float* orow_a = out + ((size_t)b * SEQ + u0 + ua) * DKE;
        float* orow_b = out + ((size_t)b * SEQ + u0 + ub) * DKE;
        #pragma unroll
        for (int jd = 0; jd < 8; jd++) {
            int cc = 8 * jd + 2 * tg;
            float2 xa = *(float2*)&Xo[ua * 68 + cc];
            float2 xb = *(float2*)&Xo[ub * 68 + cc];
            float2 ra, rb;
            ra.x = (o[jd][0] * a0A + xa.x * a1A) * invA;
            ra.y = (o[jd][1] * a0A + xa.y * a1A) * invA;
            rb.x = (o[jd][2] * a0B + xb.x * a1B) * invB;
            rb.y = (o[jd][3] * a0B + xb.y * a1B) * invB;
            *(float2*)(orow_a + cc) = ra;
            *(float2*)(orow_b + cc) = rb;
        }
    }
}

extern "C" void kernel_launch(void* const* d_in, const int* in_sizes, int n_in,
                              void* d_out, int out_size) {
    const float* Q  = (const float*)d_in[0];
    const float* K  = (const float*)d_in[1];
    const float* V  = (const float*)d_in[2];
    const float* Kr = (const float*)d_in[3];
    float* out = (float*)d_out;

    cudaFuncSetAttribute(attn_mma_kernel, cudaFuncAttributeMaxDynamicSharedMemorySize, SMEM_TOTAL);

    prologue_kernel<<<3208, 256>>>(Q, K, V, Kr);
    attn_mma_kernel<<<dim3(16, BSZ), 512, SMEM_TOTAL>>>(out);
}

// round 15
// speedup vs baseline: 1.7104x; 1.4347x over previous
#include <cuda_runtime.h>
#include <cuda_fp16.h>
#include <cstdint>

#define BSZ 16
#define SEQ 2048
#define DKE 64
#define KR_ROWS 2176
#define C_SCALE 0.1803368801111204f  /* log2(e)/sqrt(64) */

// -------- device-global fp16 scratch --------
__device__ __align__(16) __half g_qf[BSZ * SEQ * DKE];   // pre-scaled by C_SCALE
__device__ __align__(16) __half g_kf[BSZ * SEQ * DKE];
__device__ __align__(16) __half g_vf[BSZ * DKE * SEQ];   // [b][d][t]
__device__ __align__(16) __half g_krf[KR_ROWS * DKE];    // [c][d], c>=SEQ zero

__device__ __forceinline__ uint32_t smem_to_u32(const void* p) {
    uint32_t a;
    asm("{ .reg .u64 t; cvta.to.shared.u64 t, %1; cvt.u32.u64 %0, t; }" : "=r"(a) : "l"(p));
    return a;
}
__device__ __forceinline__ float ex2(float x) {
    float y;
    asm("ex2.approx.f32 %0, %1;" : "=f"(y) : "f"(x));
    return y;
}

#define LDSM4(r0, r1, r2, r3, addr) \
    asm volatile("ldmatrix.sync.aligned.m8n8.x4.shared.b16 {%0,%1,%2,%3}, [%4];" \
                 : "=r"(r0), "=r"(r1), "=r"(r2), "=r"(r3) : "r"(addr))

#define MMAF16(d, a, bb0, bb1) \
    asm volatile("mma.sync.aligned.m16n8k16.row.col.f32.f16.f16.f32 " \
                 "{%0,%1,%2,%3},{%4,%5,%6,%7},{%8,%9},{%0,%1,%2,%3};" \
                 : "+f"((d)[0]), "+f"((d)[1]), "+f"((d)[2]), "+f"((d)[3]) \
                 : "r"((a)[0]), "r"((a)[1]), "r"((a)[2]), "r"((a)[3]), "r"(bb0), "r"(bb1))

#define CP16(dst, src) \
    asm volatile("cp.async.cg.shared.global [%0], [%1], 16;" :: "r"(dst), "l"(src))
#define CP_COMMIT() asm volatile("cp.async.commit_group;")
#define CP_WAIT0()  asm volatile("cp.async.wait_group 0;")
#define PAIR_BAR(id) asm volatile("bar.sync %0, 64;" :: "r"(id) : "memory")

// -------- merged prologue: 3208 blocks x 256 threads --------
__global__ void prologue_kernel(const float* __restrict__ Q, const float* __restrict__ K,
                                const float* __restrict__ V, const float* __restrict__ Kr) {
    __shared__ float tile[32][33];
    const int bx = blockIdx.x, tid = threadIdx.x;
    if (bx < 512) {  // Q: scale + fp16
        const int base = bx * 4096 + tid * 4;
        #pragma unroll
        for (int k = 0; k < 4; k++) {
            int i = base + k * 1024;
            float4 x = *(const float4*)(Q + i);
            __half2 h0 = __float22half2_rn(make_float2(x.x * C_SCALE, x.y * C_SCALE));
            __half2 h1 = __float22half2_rn(make_float2(x.z * C_SCALE, x.w * C_SCALE));
            *(__half2*)(g_qf + i) = h0;
            *(__half2*)(g_qf + i + 2) = h1;
        }
    } else if (bx < 1024) {  // K: fp16
        const int base = (bx - 512) * 4096 + tid * 4;
        #pragma unroll
        for (int k = 0; k < 4; k++) {
            int i = base + k * 1024;
            float4 x = *(const float4*)(K + i);
            *(__half2*)(g_kf + i)     = __float22half2_rn(make_float2(x.x, x.y));
            *(__half2*)(g_kf + i + 2) = __float22half2_rn(make_float2(x.z, x.w));
        }
    } else if (bx < 3072) {  // V: transpose + fp16
        const int v = bx - 1024;
        const int b = v >> 7, s0 = (v & 63) * 32, d0 = ((v >> 6) & 1) * 32;
        const int tx = tid & 31, ty = tid >> 5;
        const float* ip = V + (size_t)b * SEQ * DKE;
        for (int i = ty; i < 32; i += 8) tile[i][tx] = ip[(size_t)(s0 + i) * DKE + d0 + tx];
        __syncthreads();
        for (int i = ty; i < 32; i += 8)
            g_vf[((size_t)b * DKE + d0 + i) * SEQ + s0 + tx] = __float2half_rn(tile[tx][i]);
    } else {  // Kr: transpose + fp16
        const int r = bx - 3072;
        const int c0 = (r % 68) * 32, d0 = (r / 68) * 32;
        const int tx = tid & 31, ty = tid >> 5;
        for (int i = ty; i < 32; i += 8) {
            int c = c0 + tx;
            tile[i][tx] = (c < SEQ) ? Kr[(size_t)(d0 + i) * SEQ + c] : 0.0f;
        }
        __syncthreads();
        for (int i = ty; i < 32; i += 8)
            g_krf[(size_t)(c0 + i) * DKE + d0 + tx] = __float2half_rn(tile[tx][i]);
    }
}

// -------- smem layout (bytes) --------
#define QF_O  0        /* fp16 128 x 144B, persistent */
#define K_O   18432    /* fp16 128 x 144B */
#define KR_O  36864    /* fp16 256 x 144B */
#define V_O   73728    /* fp16 64 x 272B ([d][t]) */
#define BSP_O 91136    /* fp16 128 x 272B: bias tile, then P tile (disjoint lifetimes) */
#define SMEM_TOTAL 125952
/* epilogue aliases */
#define XO_O 0         /* f32 128 x 68 (over QF+K) */
#define MX_O 36864     /* f32[128] (over KR) */
#define LX_O 37888

__global__ __launch_bounds__(512, 1)
void attn_mma_kernel(float* __restrict__ out) {
    extern __shared__ char smem[];
    const uint32_t sm = smem_to_u32(smem);
    const int tid = threadIdx.x, w = tid >> 5, l = tid & 31;
    const int g = l >> 2, tg = l & 3;
    const int ws = w & 7;          // row strip
    const int h = w >> 3;          // t-half this warp owns
    const int Rb = ws * 16;
    const int ua = Rb + g, ub = Rb + g + 8;
    const int bar_id = 1 + ws;
    const int b = blockIdx.y;
    const int u0 = (15 - (int)blockIdx.x) * 128;  // big tiles first
    const int c0 = 1920 - u0;

    // ---- persistent staging: Q fp16 (scaled) ----
    for (int i = tid; i < 1152; i += 512) {
        int r = i / 9, c = i % 9;
        CP16(sm + QF_O + r * 144 + c * 16,
             (const char*)(g_qf + ((size_t)b * SEQ + u0 + r) * DKE + c * 8));
    }
    CP_COMMIT();
    CP_WAIT0();
    __syncthreads();

    const int brow = l & 7;
    const int bk16 = (l >> 3) * 16;          // B-frag col bytes
    const int qko16 = ((l >> 4) & 1) * 16;   // A-frag col bytes

    // persistent Q A-fragments (serve S and bias)
    uint32_t qf[4][4];
    {
        const uint32_t qa = sm + QF_O + (uint32_t)((Rb + (l & 15)) * 144 + qko16);
        #pragma unroll
        for (int c = 0; c < 4; c++)
            LDSM4(qf[c][0], qf[c][1], qf[c][2], qf[c][3], qa + c * 32);
    }

    float m_a = -1e30f, m_b = -1e30f, l_a = 0.0f, l_b = 0.0f;
    float o[8][4];
    #pragma unroll
    for (int j = 0; j < 8; j++) { o[j][0] = o[j][1] = o[j][2] = o[j][3] = 0.0f; }

    const int nIter = u0 / 128 + 1;
    for (int it = 0; it < nIter; ++it) {
        const int t0 = it * 128;
        const int c_base = c0 + t0;
        __syncthreads();  // previous K/KR/V/P fully consumed

        // ---- stage K(it), KR window, V(it) — all fp16 ----
        for (int i = tid; i < 1152; i += 512) {
            int r = i / 9, c = i % 9;
            CP16(sm + K_O + r * 144 + c * 16,
                 (const char*)(g_kf + ((size_t)b * SEQ + t0 + r) * DKE + c * 8));
        }
        for (int i = tid; i < 2304; i += 512) {
            int r = i / 9, c = i % 9;
            CP16(sm + KR_O + r * 144 + c * 16,
                 (const char*)(g_krf + (size_t)(c_base + r) * DKE + c * 8));
        }
        for (int i = tid; i < 1088; i += 512) {
            int r = i / 17, c = i % 17;
            CP16(sm + V_O + r * 272 + c * 16,
                 (const char*)(g_vf + ((size_t)b * DKE + r) * SEQ + t0 + c * 8));
        }
        CP_COMMIT();
        CP_WAIT0();
        __syncthreads();

        // ---- S = Q K^T, single-pass fp16 (own 16 rows x own 64 t-cols) ----
        float s[8][4];
        #pragma unroll
        for (int j = 0; j < 8; j++) s[j][0] = s[j][1] = s[j][2] = s[j][3] = 0.0f;
        #pragma unroll
        for (int jp = 0; jp < 4; jp++) {
            const int j0 = 2 * jp;
            const uint32_t kb_a = sm + K_O + (uint32_t)((64 * h + 8 * j0 + brow) * 144 + bk16);
            const uint32_t kb_b = kb_a + 1152;  // next n-tile (+8 rows)
            uint32_t b0[8], b1[8];
            LDSM4(b0[0], b0[1], b0[2], b0[3], kb_a);
            LDSM4(b0[4], b0[5], b0[6], b0[7], kb_a + 64);
            LDSM4(b1[0], b1[1], b1[2], b1[3], kb_b);
            LDSM4(b1[4], b1[5], b1[6], b1[7], kb_b + 64);
            #pragma unroll
            for (int c = 0; c < 4; c++) {
                MMAF16(s[j0],     qf[c], b0[2 * c], b0[2 * c + 1]);
                MMAF16(s[j0 + 1], qf[c], b1[2 * c], b1[2 * c + 1]);
            }
        }

        // ---- bias GEMM fp16: pair's 18 window tiles split 9/9, scatter to BSP ----
        {
            __half* Bs = (__half*)(smem + BSP_O);
            const int jb0 = 14 - 2 * ws + 9 * h;
            #pragma unroll
            for (int jj = 0; jj < 9; jj++) {
                const int jb = jb0 + jj;
                uint32_t kb[8];
                const uint32_t ab = sm + KR_O + (uint32_t)((8 * jb + brow) * 144 + bk16);
                LDSM4(kb[0], kb[1], kb[2], kb[3], ab);
                LDSM4(kb[4], kb[5], kb[6], kb[7], ab + 64);
                float d[4] = {0, 0, 0, 0};
                #pragma unroll
                for (int c = 0; c < 4; c++)
                    MMAF16(d, qf[c], kb[2 * c], kb[2 * c + 1]);
                int cc = 8 * jb + 2 * tg;
                int ta = cc + ua - 127, tb = cc + ub - 127;
                if ((unsigned)ta < 128u)       Bs[ua * 136 + ta]     = __float2half_rn(d[0]);
                if ((unsigned)(ta + 1) < 128u) Bs[ua * 136 + ta + 1] = __float2half_rn(d[1]);
                if ((unsigned)tb < 128u)       Bs[ub * 136 + tb]     = __float2half_rn(d[2]);
                if ((unsigned)(tb + 1) < 128u) Bs[ub * 136 + tb + 1] = __float2half_rn(d[3]);
            }
        }
        PAIR_BAR(bar_id);  // both halves' bias scatter visible to the pair

        // ---- logits (pre-scaled; just add bias) + causal mask ----
        {
            const __half* Bs = (const __half*)(smem + BSP_O);
            #pragma unroll
            for (int j = 0; j < 8; j++) {
                int cc = 64 * h + 8 * j + 2 * tg;
                __half2 ba = *(__half2*)&Bs[ua * 136 + cc];
                __half2 bb = *(__half2*)&Bs[ub * 136 + cc];
                s[j][0] += __half2float(ba.x);
                s[j][1] += __half2float(ba.y);
                s[j][2] += __half2float(bb.x);
                s[j][3] += __half2float(bb.y);
            }
        }
        if (t0 == u0) {
            #pragma unroll
            for (int j = 0; j < 8; j++) {
                int cc = 64 * h + 8 * j + 2 * tg;
                if (cc > ua)     s[j][0] = -1e30f;
                if (cc + 1 > ua) s[j][1] = -1e30f;
                if (cc > ub)     s[j][2] = -1e30f;
                if (cc + 1 > ub) s[j][3] = -1e30f;
            }
        }

        // ---- warp-local online softmax ----
        float ma = -1e30f, mb = -1e30f;
        #pragma unroll
        for (int j = 0; j < 8; j++) {
            ma = fmaxf(ma, fmaxf(s[j][0], s[j][1]));
            mb = fmaxf(mb, fmaxf(s[j][2], s[j][3]));
        }
        ma = fmaxf(ma, __shfl_xor_sync(0xffffffffu, ma, 1));
        ma = fmaxf(ma, __shfl_xor_sync(0xffffffffu, ma, 2));
        mb = fmaxf(mb, __shfl_xor_sync(0xffffffffu, mb, 1));
        mb = fmaxf(mb, __shfl_xor_sync(0xffffffffu, mb, 2));
        const float mna = fmaxf(m_a, ma), mnb = fmaxf(m_b, mb);
        const float alfa = ex2(m_a - mna), alfb = ex2(m_b - mnb);
        m_a = mna; m_b = mnb;

        // exp; write P fp16 into BSP (own rows, own half cols — overwrites consumed bias)
        float pa = 0.0f, pb = 0.0f;
        #pragma unroll
        for (int j = 0; j < 8; j++) {
            const int cc = 64 * h + 8 * j + 2 * tg;
            float p0 = ex2(s[j][0] - mna);
            float p1 = ex2(s[j][1] - mna);
            float p2 = ex2(s[j][2] - mnb);
            float p3 = ex2(s[j][3] - mnb);
            pa += p0 + p1;
            pb += p2 + p3;
            *(__half2*)(smem + BSP_O + ua * 272 + cc * 2) = __float22half2_rn(make_float2(p0, p1));
            *(__half2*)(smem + BSP_O + ub * 272 + cc * 2) = __float22half2_rn(make_float2(p2, p3));
        }
        __syncwarp();
        pa += __shfl_xor_sync(0xffffffffu, pa, 1);
        pa += __shfl_xor_sync(0xffffffffu, pa, 2);
        pb += __shfl_xor_sync(0xffffffffu, pb, 1);
        pb += __shfl_xor_sync(0xffffffffu, pb, 2);
        l_a = l_a * alfa + pa;
        l_b = l_b * alfb + pb;
        #pragma unroll
        for (int j = 0; j < 8; j++) {
            o[j][0] *= alfa; o[j][1] *= alfa;
            o[j][2] *= alfb; o[j][3] *= alfb;
        }

        // ---- partial O += P V, single-pass fp16 (own t-half, all 64 d) ----
        {
            uint32_t pf[4][4];
            const uint32_t pa_b = sm + BSP_O +
                (uint32_t)((Rb + (l & 15)) * 272 + 128 * h + qko16);
            #pragma unroll
            for (int c = 0; c < 4; c++)
                LDSM4(pf[c][0], pf[c][1], pf[c][2], pf[c][3], pa_b + c * 32);
            #pragma unroll
            for (int jq = 0; jq < 4; jq++) {
                const int jd0 = 2 * jq;
                const uint32_t vb_a = sm + V_O +
                    (uint32_t)((8 * jd0 + brow) * 272 + 128 * h + bk16);
                const uint32_t vb_b = vb_a + 2176;  // +8 d-rows
                uint32_t v0[8], v1[8];
                LDSM4(v0[0], v0[1], v0[2], v0[3], vb_a);
                LDSM4(v0[4], v0[5], v0[6], v0[7], vb_a + 64);
                LDSM4(v1[0], v1[1], v1[2], v1[3], vb_b);
                LDSM4(v1[4], v1[5], v1[6], v1[7], vb_b + 64);
                #pragma unroll
                for (int c = 0; c < 4; c++) {
                    MMAF16(o[jd0],     pf[c], v0[2 * c], v0[2 * c + 1]);
                    MMAF16(o[jd0 + 1], pf[c], v1[2 * c], v1[2 * c + 1]);
                }
            }
        }
    }

    // ---- epilogue: merge half-softmax partials ----
    __syncthreads();
    float* Xo = (float*)(smem + XO_O);
    float* Mx = (float*)(smem + MX_O);
    float* Lx = (float*)(smem + LX_O);
    if (h == 1) {
        #pragma unroll
        for (int jd = 0; jd < 8; jd++) {
            int cc = 8 * jd + 2 * tg;
            *(float2*)&Xo[ua * 68 + cc] = make_float2(o[jd][0], o[jd][1]);
            *(float2*)&Xo[ub * 68 + cc] = make_float2(o[jd][2], o[jd][3]);
        }
        if (tg == 0) { Mx[ua] = m_a; Mx[ub] = m_b; Lx[ua] = l_a; Lx[ub] = l_b; }
    }
    PAIR_BAR(bar_id);
    if (h == 0) {
        const float m1a = Mx[ua], m1b = Mx[ub];
        const float l1a = Lx[ua], l1b = Lx[ub];
        const float mA = fmaxf(m_a, m1a), mB = fmaxf(m_b, m1b);
        const float a0A = ex2(m_a - mA), a1A = ex2(m1a - mA);
        const float a0B = ex2(m_b - mB), a1B = ex2(m1b - mB);
        const float invA = 1.0f / (l_a * a0A + l1a * a1A);
        const float invB = 1.0f / (l_b * a0B + l1b * a1B);
        float* orow_a = out + ((size_t)b * SEQ + u0 + ua) * DKE;
        float* orow_b = out + ((size_t)b * SEQ + u0 + ub) * DKE;
        #pragma unroll
        for (int jd = 0; jd < 8; jd++) {
            int cc = 8 * jd + 2 * tg;
            float2 xa = *(float2*)&Xo[ua * 68 + cc];
            float2 xb = *(float2*)&Xo[ub * 68 + cc];
            float2 ra, rb;
            ra.x = (o[jd][0] * a0A + xa.x * a1A) * invA;
            ra.y = (o[jd][1] * a0A + xa.y * a1A) * invA;
            rb.x = (o[jd][2] * a0B + xb.x * a1B) * invB;
            rb.y = (o[jd][3] * a0B + xb.y * a1B) * invB;
            *(float2*)(orow_a + cc) = ra;
            *(float2*)(orow_b + cc) = rb;
        }
    }
}

extern "C" void kernel_launch(void* const* d_in, const int* in_sizes, int n_in,
                              void* d_out, int out_size) {
    const float* Q  = (const float*)d_in[0];
    const float* K  = (const float*)d_in[1];
    const float* V  = (const float*)d_in[2];
    const float* Kr = (const float*)d_in[3];
    float* out = (float*)d_out;

    cudaFuncSetAttribute(attn_mma_kernel, cudaFuncAttributeMaxDynamicSharedMemorySize, SMEM_TOTAL);

    prologue_kernel<<<3208, 256>>>(Q, K, V, Kr);
    attn_mma_kernel<<<dim3(16, BSZ), 512, SMEM_TOTAL>>>(out);
}

// round 16
// speedup vs baseline: 1.9238x; 1.1248x over previous
#include <cuda_runtime.h>
#include <cuda_fp16.h>
#include <cstdint>

#define BSZ 16
#define SEQ 2048
#define DKE 64
#define KR_ROWS 2176
#define C_SCALE 0.1803368801111204f  /* log2(e)/sqrt(64) */

// -------- device-global fp16 scratch --------
__device__ __align__(16) __half g_qf[BSZ * SEQ * DKE];   // pre-scaled by C_SCALE
__device__ __align__(16) __half g_kf[BSZ * SEQ * DKE];
__device__ __align__(16) __half g_vf[BSZ * DKE * SEQ];   // [b][d][t]
__device__ __align__(16) __half g_krf[KR_ROWS * DKE];    // [c][d], c>=SEQ zero

__device__ __forceinline__ uint32_t smem_to_u32(const void* p) {
    uint32_t a;
    asm("{ .reg .u64 t; cvta.to.shared.u64 t, %1; cvt.u32.u64 %0, t; }" : "=r"(a) : "l"(p));
    return a;
}
__device__ __forceinline__ float ex2(float x) {
    float y;
    asm("ex2.approx.f32 %0, %1;" : "=f"(y) : "f"(x));
    return y;
}
__device__ __forceinline__ uint32_t h2pack(float a, float b) {
    __half2 v = __float22half2_rn(make_float2(a, b));
    return *(uint32_t*)&v;
}

#define LDSM4(r0, r1, r2, r3, addr) \
    asm volatile("ldmatrix.sync.aligned.m8n8.x4.shared.b16 {%0,%1,%2,%3}, [%4];" \
                 : "=r"(r0), "=r"(r1), "=r"(r2), "=r"(r3) : "r"(addr))

#define MMAF16(d, a, bb0, bb1) \
    asm volatile("mma.sync.aligned.m16n8k16.row.col.f32.f16.f16.f32 " \
                 "{%0,%1,%2,%3},{%4,%5,%6,%7},{%8,%9},{%0,%1,%2,%3};" \
                 : "+f"((d)[0]), "+f"((d)[1]), "+f"((d)[2]), "+f"((d)[3]) \
                 : "r"((a)[0]), "r"((a)[1]), "r"((a)[2]), "r"((a)[3]), "r"(bb0), "r"(bb1))

#define CP16(dst, src) \
    asm volatile("cp.async.cg.shared.global [%0], [%1], 16;" :: "r"(dst), "l"(src))
#define CP_COMMIT() asm volatile("cp.async.commit_group;")
#define CP_WAIT0()  asm volatile("cp.async.wait_group 0;")
#define PAIR_BAR(id) asm volatile("bar.sync %0, 64;" :: "r"(id) : "memory")

// -------- merged prologue: 3208 blocks x 256 threads --------
__global__ void prologue_kernel(const float* __restrict__ Q, const float* __restrict__ K,
                                const float* __restrict__ V, const float* __restrict__ Kr) {
    __shared__ float tile[32][33];
    const int bx = blockIdx.x, tid = threadIdx.x;
    if (bx < 512) {  // Q: scale + fp16
        const int base = bx * 4096 + tid * 4;
        #pragma unroll
        for (int k = 0; k < 4; k++) {
            int i = base + k * 1024;
            float4 x = *(const float4*)(Q + i);
            *(__half2*)(g_qf + i)     = __float22half2_rn(make_float2(x.x * C_SCALE, x.y * C_SCALE));
            *(__half2*)(g_qf + i + 2) = __float22half2_rn(make_float2(x.z * C_SCALE, x.w * C_SCALE));
        }
    } else if (bx < 1024) {  // K: fp16
        const int base = (bx - 512) * 4096 + tid * 4;
        #pragma unroll
        for (int k = 0; k < 4; k++) {
            int i = base + k * 1024;
            float4 x = *(const float4*)(K + i);
            *(__half2*)(g_kf + i)     = __float22half2_rn(make_float2(x.x, x.y));
            *(__half2*)(g_kf + i + 2) = __float22half2_rn(make_float2(x.z, x.w));
        }
    } else if (bx < 3072) {  // V: transpose + fp16
        const int v = bx - 1024;
        const int b = v >> 7, s0 = (v & 63) * 32, d0 = ((v >> 6) & 1) * 32;
        const int tx = tid & 31, ty = tid >> 5;
        const float* ip = V + (size_t)b * SEQ * DKE;
        for (int i = ty; i < 32; i += 8) tile[i][tx] = ip[(size_t)(s0 + i) * DKE + d0 + tx];
        __syncthreads();
        for (int i = ty; i < 32; i += 8)
            g_vf[((size_t)b * DKE + d0 + i) * SEQ + s0 + tx] = __float2half_rn(tile[tx][i]);
    } else {  // Kr: transpose + fp16
        const int r = bx - 3072;
        const int c0 = (r % 68) * 32, d0 = (r / 68) * 32;
        const int tx = tid & 31, ty = tid >> 5;
        for (int i = ty; i < 32; i += 8) {
            int c = c0 + tx;
            tile[i][tx] = (c < SEQ) ? Kr[(size_t)(d0 + i) * SEQ + c] : 0.0f;
        }
        __syncthreads();
        for (int i = ty; i < 32; i += 8)
            g_krf[(size_t)(c0 + i) * DKE + d0 + tx] = __float2half_rn(tile[tx][i]);
    }
}

// -------- smem layout (bytes) --------
#define QF_O   0        /* fp16 128 x 144B, persistent */
#define BUF0_O 18432    /* double-buffered tile set */
#define BUF1_O 91136
#define KK_O   0        /* within buffer: fp16 128 x 144B */
#define KRR_O  18432    /* within buffer: fp16 256 x 144B */
#define VV_O   55296    /* within buffer: fp16 64 x 272B */
#define BS_O   163840   /* fp16 128 x 136 halves (272B stride), bias only */
#define SMEM_TOTAL 198656
/* epilogue aliases (over BUF0) */
#define XO_O 18432
#define MX_O 53248
#define LX_O 54272

__device__ __forceinline__ void issue_tiles(uint32_t bufd, int b, int t0, int c_base, int tid) {
    for (int i = tid; i < 1152; i += 512) {
        int r = i / 9, c = i % 9;
        CP16(bufd + KK_O + r * 144 + c * 16,
             (const char*)(g_kf + ((size_t)b * SEQ + t0 + r) * DKE + c * 8));
    }
    for (int i = tid; i < 2304; i += 512) {
        int r = i / 9, c = i % 9;
        CP16(bufd + KRR_O + r * 144 + c * 16,
             (const char*)(g_krf + (size_t)(c_base + r) * DKE + c * 8));
    }
    for (int i = tid; i < 1088; i += 512) {
        int r = i / 17, c = i % 17;
        CP16(bufd + VV_O + r * 272 + c * 16,
             (const char*)(g_vf + ((size_t)b * DKE + r) * SEQ + t0 + c * 8));
    }
    CP_COMMIT();
}

__global__ __launch_bounds__(512, 1)
void attn_mma_kernel(float* __restrict__ out) {
    extern __shared__ char smem[];
    const uint32_t sm = smem_to_u32(smem);
    const int tid = threadIdx.x, w = tid >> 5, l = tid & 31;
    const int g = l >> 2, tg = l & 3;
    const int ws = w & 7;          // row strip
    const int h = w >> 3;          // t-half this warp owns
    const int Rb = ws * 16;
    const int ua = Rb + g, ub = Rb + g + 8;
    const int bar_id = 1 + ws;
    const int b = blockIdx.y;
    const int u0 = (15 - (int)blockIdx.x) * 128;  // big tiles first
    const int c0 = 1920 - u0;

    // ---- prologue staging: Q (persistent) + buffer0 tiles for it=0 ----
    for (int i = tid; i < 1152; i += 512) {
        int r = i / 9, c = i % 9;
        CP16(sm + QF_O + r * 144 + c * 16,
             (const char*)(g_qf + ((size_t)b * SEQ + u0 + r) * DKE + c * 8));
    }
    issue_tiles(sm + BUF0_O, b, 0, c0, tid);
    CP_WAIT0();
    __syncthreads();

    const int brow = l & 7;
    const int bk16 = (l >> 3) * 16;          // B-frag col bytes
    const int qko16 = ((l >> 4) & 1) * 16;   // A-frag col bytes

    // persistent Q A-fragments (serve S and bias)
    uint32_t qf[4][4];
    {
        const uint32_t qa = sm + QF_O + (uint32_t)((Rb + (l & 15)) * 144 + qko16);
        #pragma unroll
        for (int c = 0; c < 4; c++)
            LDSM4(qf[c][0], qf[c][1], qf[c][2], qf[c][3], qa + c * 32);
    }

    float m_a = -1e30f, m_b = -1e30f, l_a = 0.0f, l_b = 0.0f;
    float o[8][4];
    #pragma unroll
    for (int j = 0; j < 8; j++) { o[j][0] = o[j][1] = o[j][2] = o[j][3] = 0.0f; }

    const int nIter = u0 / 128 + 1;
    for (int it = 0; it < nIter; ++it) {
        const int t0 = it * 128;
        const uint32_t bufc = sm + (((it & 1) == 0) ? BUF0_O : BUF1_O);

        // prefetch next iteration's tiles into the other buffer
        if (it + 1 < nIter) {
            const uint32_t bufn = sm + (((it & 1) == 0) ? BUF1_O : BUF0_O);
            issue_tiles(bufn, b, t0 + 128, c0 + t0 + 128, tid);
        }

        // ---- S = Q K^T, single-pass fp16 (own 16 rows x own 64 t-cols) ----
        float s[8][4];
        #pragma unroll
        for (int j = 0; j < 8; j++) s[j][0] = s[j][1] = s[j][2] = s[j][3] = 0.0f;
        #pragma unroll
        for (int jp = 0; jp < 4; jp++) {
            const int j0 = 2 * jp;
            const uint32_t kb_a = bufc + KK_O + (uint32_t)((64 * h + 8 * j0 + brow) * 144 + bk16);
            const uint32_t kb_b = kb_a + 1152;  // next n-tile (+8 rows)
            uint32_t b0[8], b1[8];
            LDSM4(b0[0], b0[1], b0[2], b0[3], kb_a);
            LDSM4(b0[4], b0[5], b0[6], b0[7], kb_a + 64);
            LDSM4(b1[0], b1[1], b1[2], b1[3], kb_b);
            LDSM4(b1[4], b1[5], b1[6], b1[7], kb_b + 64);
            #pragma unroll
            for (int c = 0; c < 4; c++) {
                MMAF16(s[j0],     qf[c], b0[2 * c], b0[2 * c + 1]);
                MMAF16(s[j0 + 1], qf[c], b1[2 * c], b1[2 * c + 1]);
            }
        }

        // ---- bias GEMM fp16: pair's 18 window tiles split 9/9, scatter to BS ----
        {
            __half* Bs = (__half*)(smem + BS_O);
            const int jb0 = 14 - 2 * ws + 9 * h;
            #pragma unroll
            for (int jj = 0; jj < 9; jj++) {
                const int jb = jb0 + jj;
                uint32_t kb[8];
                const uint32_t ab = bufc + KRR_O + (uint32_t)((8 * jb + brow) * 144 + bk16);
                LDSM4(kb[0], kb[1], kb[2], kb[3], ab);
                LDSM4(kb[4], kb[5], kb[6], kb[7], ab + 64);
                float d[4] = {0, 0, 0, 0};
                #pragma unroll
                for (int c = 0; c < 4; c++)
                    MMAF16(d, qf[c], kb[2 * c], kb[2 * c + 1]);
                int cc = 8 * jb + 2 * tg;
                int ta = cc + ua - 127, tb = cc + ub - 127;
                if ((unsigned)ta < 128u)       Bs[ua * 136 + ta]     = __float2half_rn(d[0]);
                if ((unsigned)(ta + 1) < 128u) Bs[ua * 136 + ta + 1] = __float2half_rn(d[1]);
                if ((unsigned)tb < 128u)       Bs[ub * 136 + tb]     = __float2half_rn(d[2]);
                if ((unsigned)(tb + 1) < 128u) Bs[ub * 136 + tb + 1] = __float2half_rn(d[3]);
            }
        }
        PAIR_BAR(bar_id);  // both halves' bias scatter visible to the pair

        // ---- logits (pre-scaled; just add bias) + causal mask ----
        {
            const __half* Bs = (const __half*)(smem + BS_O);
            #pragma unroll
            for (int j = 0; j < 8; j++) {
                int cc = 64 * h + 8 * j + 2 * tg;
                __half2 ba = *(__half2*)&Bs[ua * 136 + cc];
                __half2 bb = *(__half2*)&Bs[ub * 136 + cc];
                s[j][0] += __half2float(ba.x);
                s[j][1] += __half2float(ba.y);
                s[j][2] += __half2float(bb.x);
                s[j][3] += __half2float(bb.y);
            }
        }
        if (t0 == u0) {
            #pragma unroll
            for (int j = 0; j < 8; j++) {
                int cc = 64 * h + 8 * j + 2 * tg;
                if (cc > ua)     s[j][0] = -1e30f;
                if (cc + 1 > ua) s[j][1] = -1e30f;
                if (cc > ub)     s[j][2] = -1e30f;
                if (cc + 1 > ub) s[j][3] = -1e30f;
            }
        }

        // ---- warp-local online softmax ----
        float ma = -1e30f, mb = -1e30f;
        #pragma unroll
        for (int j = 0; j < 8; j++) {
            ma = fmaxf(ma, fmaxf(s[j][0], s[j][1]));
            mb = fmaxf(mb, fmaxf(s[j][2], s[j][3]));
        }
        ma = fmaxf(ma, __shfl_xor_sync(0xffffffffu, ma, 1));
        ma = fmaxf(ma, __shfl_xor_sync(0xffffffffu, ma, 2));
        mb = fmaxf(mb, __shfl_xor_sync(0xffffffffu, mb, 1));
        mb = fmaxf(mb, __shfl_xor_sync(0xffffffffu, mb, 2));
        const float mna = fmaxf(m_a, ma), mnb = fmaxf(m_b, mb);
        const float alfa = ex2(m_a - mna), alfb = ex2(m_b - mnb);
        m_a = mna; m_b = mnb;

        // exp in place + partial sums
        float pa = 0.0f, pb = 0.0f;
        #pragma unroll
        for (int j = 0; j < 8; j++) {
            s[j][0] = ex2(s[j][0] - mna);
            s[j][1] = ex2(s[j][1] - mna);
            s[j][2] = ex2(s[j][2] - mnb);
            s[j][3] = ex2(s[j][3] - mnb);
            pa += s[j][0] + s[j][1];
            pb += s[j][2] + s[j][3];
        }

        // P -> fp16 A-fragments by direct register repack (no smem round-trip)
        uint32_t pf[4][4];
        #pragma unroll
        for (int c = 0; c < 4; c++) {
            pf[c][0] = h2pack(s[2 * c][0],     s[2 * c][1]);
            pf[c][1] = h2pack(s[2 * c][2],     s[2 * c][3]);
            pf[c][2] = h2pack(s[2 * c + 1][0], s[2 * c + 1][1]);
            pf[c][3] = h2pack(s[2 * c + 1][2], s[2 * c + 1][3]);
        }

        pa += __shfl_xor_sync(0xffffffffu, pa, 1);
        pa += __shfl_xor_sync(0xffffffffu, pa, 2);
        pb += __shfl_xor_sync(0xffffffffu, pb, 1);
        pb += __shfl_xor_sync(0xffffffffu, pb, 2);
        l_a = l_a * alfa + pa;
        l_b = l_b * alfb + pb;
        #pragma unroll
        for (int j = 0; j < 8; j++) {
            o[j][0] *= alfa; o[j][1] *= alfa;
            o[j][2] *= alfb; o[j][3] *= alfb;
        }

        // ---- partial O += P V, single-pass fp16 (own t-half, all 64 d) ----
        #pragma unroll
        for (int jq = 0; jq < 4; jq++) {
            const int jd0 = 2 * jq;
            const uint32_t vb_a = bufc + VV_O +
                (uint32_t)((8 * jd0 + brow) * 272 + 128 * h + bk16);
            const uint32_t vb_b = vb_a + 2176;  // +8 d-rows
            uint32_t v0[8], v1[8];
            LDSM4(v0[0], v0[1], v0[2], v0[3], vb_a);
            LDSM4(v0[4], v0[5], v0[6], v0[7], vb_a + 64);
            LDSM4(v1[0], v1[1], v1[2], v1[3], vb_b);
            LDSM4(v1[4], v1[5], v1[6], v1[7], vb_b + 64);
            #pragma unroll
            for (int c = 0; c < 4; c++) {
                MMAF16(o[jd0],     pf[c], v0[2 * c], v0[2 * c + 1]);
                MMAF16(o[jd0 + 1], pf[c], v1[2 * c], v1[2 * c + 1]);
            }
        }

        // next buffer landed; barrier separates BS reuse + buffer swap
        CP_WAIT0();
        __syncthreads();
    }

    // ---- epilogue: merge half-softmax partials ----
    float* Xo = (float*)(smem + XO_O);
    float* Mx = (float*)(smem + MX_O);
    float* Lx = (float*)(smem + LX_O);
    if (h == 1) {
        #pragma unroll
        for (int jd = 0; jd < 8; jd++) {
            int cc = 8 * jd + 2 * tg;
            *(float2*)&Xo[ua * 68 + cc] = make_float2(o[jd][0], o[jd][1]);
            *(float2*)&Xo[ub * 68 + cc] = make_float2(o[jd][2], o[jd][3]);
        }
        if (tg == 0) { Mx[ua] = m_a; Mx[ub] = m_b; Lx[ua] = l_a; Lx[ub] = l_b; }
    }
    PAIR_BAR(bar_id);
    if (h == 0) {
        const float m1a = Mx[ua], m1b = Mx[ub];
        const float l1a = Lx[ua], l1b = Lx[ub];
        const float mA = fmaxf(m_a, m1a), mB = fmaxf(m_b, m1b);
        const float a0A = ex2(m_a - mA), a1A = ex2(m1a - mA);
        const float a0B = ex2(m_b - mB), a1B = ex2(m1b - mB);
        const float invA = 1.0f / (l_a * a0A + l1a * a1A);
        const float invB = 1.0f / (l_b * a0B + l1b * a1B);
        float* orow_a = out + ((size_t)b * SEQ + u0 + ua) * DKE;
        float* orow_b = out + ((size_t)b * SEQ + u0 + ub) * DKE;
        #pragma unroll
        for (int jd = 0; jd < 8; jd++) {
            int cc = 8 * jd + 2 * tg;
            float2 xa = *(float2*)&Xo[ua * 68 + cc];
            float2 xb = *(float2*)&Xo[ub * 68 + cc];
            float2 ra, rb;
            ra.x = (o[jd][0] * a0A + xa.x * a1A) * invA;
            ra.y = (o[jd][1] * a0A + xa.y * a1A) * invA;
            rb.x = (o[jd][2] * a0B + xb.x * a1B) * invB;
            rb.y = (o[jd][3] * a0B + xb.y * a1B) * invB;
            *(float2*)(orow_a + cc) = ra;
            *(float2*)(orow_b + cc) = rb;
        }
    }
}

extern "C" void kernel_launch(void* const* d_in, const int* in_sizes, int n_in,
                              void* d_out, int out_size) {
    const float* Q  = (const float*)d_in[0];
    const float* K  = (const float*)d_in[1];
    const float* V  = (const float*)d_in[2];
    const float* Kr = (const float*)d_in[3];
    float* out = (float*)d_out;

    cudaFuncSetAttribute(attn_mma_kernel, cudaFuncAttributeMaxDynamicSharedMemorySize, SMEM_TOTAL);

    prologue_kernel<<<3208, 256>>>(Q, K, V, Kr);
    attn_mma_kernel<<<dim3(16, BSZ), 512, SMEM_TOTAL>>>(out);
}